// round 2
// baseline (speedup 1.0000x reference)
#include <cuda_runtime.h>
#include <math.h>

#define B_   2
#define S_   2048
#define D_   1024
#define H_   16
#define DK_  64
#define M_   16
#define L_   4
#define DFF_ 4096
#define VT_  69
#define VS_  69
#define FD_  34
#define BS_  (B_*S_)
#define CCH  32
#define TCH  64
#define EPSF 1e-6f

// ---------------- scratch (static device memory; no allocations) -------------
__device__ float g_emb2[VS_*D_];
__device__ float g_x  [BS_*D_];
__device__ float g_xn [BS_*D_];
__device__ float g_q  [BS_*D_];
__device__ float g_k  [BS_*D_];
__device__ float g_v  [BS_*D_];
__device__ float g_qp [BS_*H_*M_];
__device__ float g_kp [BS_*H_*M_];
__device__ float g_att[BS_*D_];
__device__ float g_h1 [(size_t)BS_*DFF_];
__device__ float g_ckv[(size_t)B_*H_*CCH*M_*DK_];
__device__ float g_ck [B_*H_*CCH*M_];
__device__ float g_gate[B_*H_];

// ---------------- fused embedding table: emb2[v] = id_embed[v] + g*keep*(feat@proj^T)
__global__ void embtbl_kernel(const float* __restrict__ id_embed,
                              const float* __restrict__ feat_proj,
                              const float* __restrict__ gammap,
                              const float* __restrict__ feat_tbl)
{
    int v = blockIdx.x;
    float gscale = gammap[0] * ((v >= 10) ? 1.f : 0.f);
    __shared__ float ft[FD_];
    if (threadIdx.x < FD_) ft[threadIdx.x] = feat_tbl[v*FD_ + threadIdx.x];
    __syncthreads();
    for (int d = threadIdx.x; d < D_; d += blockDim.x) {
        float dot = 0.f;
        #pragma unroll
        for (int f = 0; f < FD_; f++) dot += ft[f] * feat_proj[d*FD_ + f];
        g_emb2[v*D_ + d] = id_embed[(size_t)v*D_ + d] + gscale * dot;
    }
}

// ---------------- x = emb2[ids] + pe ----------------------------------------
__global__ void xinit_kernel(const int* __restrict__ ids, const float* __restrict__ pe)
{
    int idx = blockIdx.x*blockDim.x + threadIdx.x;
    if (idx >= BS_*D_) return;
    int d = idx % D_;
    int bs = idx / D_;
    int s = bs % S_;
    g_x[idx] = g_emb2[ids[bs]*D_ + d] + pe[(size_t)s*D_ + d];
}

// ---------------- per-user head gate softmax --------------------------------
__global__ void gate_kernel(const int* __restrict__ user_ids,
                            const float* __restrict__ gl)
{
    int b = blockIdx.x;
    int lane = threadIdx.x;
    float v = (lane < H_) ? gl[(size_t)user_ids[b]*H_ + lane] : -1e30f;
    float mx = v;
    #pragma unroll
    for (int o = 16; o > 0; o >>= 1) mx = fmaxf(mx, __shfl_xor_sync(~0u, mx, o));
    float e = (lane < H_) ? expf(v - mx) : 0.f;
    float s = e;
    #pragma unroll
    for (int o = 16; o > 0; o >>= 1) s += __shfl_xor_sync(~0u, s, o);
    if (lane < H_) g_gate[b*H_ + lane] = e / s;
}

// ---------------- LayerNorm (unbiased var, eps on std) ----------------------
__global__ void __launch_bounds__(256) ln_kernel(const float* __restrict__ X,
                                                 const float* __restrict__ alpha,
                                                 const float* __restrict__ beta,
                                                 float* __restrict__ Y)
{
    int row = blockIdx.x;
    const float* x = X + (size_t)row*D_;
    float s = 0.f, s2 = 0.f;
    for (int d = threadIdx.x; d < D_; d += blockDim.x) {
        float v = x[d]; s += v; s2 += v*v;
    }
    __shared__ float red[64];
    #pragma unroll
    for (int o = 16; o > 0; o >>= 1) {
        s  += __shfl_down_sync(~0u, s,  o);
        s2 += __shfl_down_sync(~0u, s2, o);
    }
    int w = threadIdx.x >> 5, lane = threadIdx.x & 31;
    if (lane == 0) { red[w] = s; red[w+32] = s2; }
    __syncthreads();
    if (w == 0) {
        s  = (lane < 8) ? red[lane]    : 0.f;
        s2 = (lane < 8) ? red[lane+32] : 0.f;
        #pragma unroll
        for (int o = 4; o > 0; o >>= 1) {
            s  += __shfl_down_sync(~0u, s,  o);
            s2 += __shfl_down_sync(~0u, s2, o);
        }
        if (lane == 0) { red[0] = s; red[1] = s2; }
    }
    __syncthreads();
    float mu  = red[0] / (float)D_;
    float var = (red[1] - (float)D_*mu*mu) / (float)(D_-1);
    float inv = 1.f / (sqrtf(fmaxf(var, 0.f)) + EPSF);
    float* y = Y + (size_t)row*D_;
    for (int d = threadIdx.x; d < D_; d += blockDim.x)
        y[d] = alpha[d] * (x[d] - mu) * inv + beta[d];
}

// ---------------- SGEMM  C[i,j] = sum_k A[i,k]*B[j,k]  (NT) ------------------
// EPI: 0 plain, 1 +bias, 2 +bias+gelu, 3 +residual, 4 +bias+residual
template<int EPI>
__global__ void __launch_bounds__(256) sgemm_nt(
    const float* __restrict__ A, const float* __restrict__ Bm,
    const float* __restrict__ bias, const float* __restrict__ res,
    float* __restrict__ Cc, int Mr, int Nc, int K)
{
    __shared__ __align__(16) float As[8][128+4];
    __shared__ __align__(16) float Bs[8][128+4];
    int t  = threadIdx.x;
    int tx = t & 15, ty = t >> 4;
    int m0 = blockIdx.y * 128;
    int n0 = blockIdx.x * 128;
    int lr = t >> 1;
    int lc = (t & 1) * 4;

    float acc[8][8];
    #pragma unroll
    for (int i = 0; i < 8; i++)
        #pragma unroll
        for (int j = 0; j < 8; j++) acc[i][j] = 0.f;

    for (int kt = 0; kt < K; kt += 8) {
        float4 av = *(const float4*)(A + (size_t)(m0+lr)*K + kt + lc);
        float4 bv = make_float4(0.f,0.f,0.f,0.f);
        int brow = n0 + lr;
        if (brow < Nc) bv = *(const float4*)(Bm + (size_t)brow*K + kt + lc);
        __syncthreads();
        As[lc+0][lr]=av.x; As[lc+1][lr]=av.y; As[lc+2][lr]=av.z; As[lc+3][lr]=av.w;
        Bs[lc+0][lr]=bv.x; Bs[lc+1][lr]=bv.y; Bs[lc+2][lr]=bv.z; Bs[lc+3][lr]=bv.w;
        __syncthreads();
        #pragma unroll
        for (int kk = 0; kk < 8; kk++) {
            float a[8], b[8];
            *(float4*)(a  ) = *(const float4*)&As[kk][ty*8  ];
            *(float4*)(a+4) = *(const float4*)&As[kk][ty*8+4];
            *(float4*)(b  ) = *(const float4*)&Bs[kk][tx*8  ];
            *(float4*)(b+4) = *(const float4*)&Bs[kk][tx*8+4];
            #pragma unroll
            for (int i = 0; i < 8; i++)
                #pragma unroll
                for (int j = 0; j < 8; j++) acc[i][j] += a[i]*b[j];
        }
    }
    #pragma unroll
    for (int i = 0; i < 8; i++) {
        int row = m0 + ty*8 + i;
        #pragma unroll
        for (int j = 0; j < 8; j++) {
            int col = n0 + tx*8 + j;
            if (col < Nc) {
                float v = acc[i][j];
                if (EPI==1 || EPI==2 || EPI==4) v += bias[col];
                if (EPI==2) {
                    float xg = v;
                    v = 0.5f*xg*(1.f + tanhf(0.7978845608028654f*(xg + 0.044715f*xg*xg*xg)));
                }
                if (EPI==3 || EPI==4) v += res[(size_t)row*Nc + col];
                Cc[(size_t)row*Nc + col] = v;
            }
        }
    }
}

// ---------------- feature map: p = exp(-0.5*(q@omega^T)^2), row-normalized ---
__global__ void __launch_bounds__(128) featmap_kernel(
    const float* __restrict__ Q, const float* __restrict__ omega,
    float* __restrict__ P)
{
    int wl = threadIdx.x >> 5;
    int lane = threadIdx.x & 31;
    int gw = blockIdx.x*4 + wl;                 // token-head index in [0, BS*H)
    int h  = gw % H_;
    int bs = gw / H_;
    const float* q = Q + (size_t)bs*D_ + h*DK_;
    __shared__ float sq[4][DK_];
    sq[wl][lane]    = q[lane];
    sq[wl][lane+32] = q[lane+32];
    __syncwarp();
    float t = 0.f;
    if (lane < M_) {
        float dot = 0.f;
        #pragma unroll
        for (int d = 0; d < DK_; d++) dot += sq[wl][d]*omega[lane*DK_ + d];
        t = expf(-0.5f*dot*dot);
    }
    float s = t;
    #pragma unroll
    for (int o = 16; o > 0; o >>= 1) s += __shfl_xor_sync(~0u, s, o);
    if (lane < M_) P[(size_t)gw*M_ + lane] = t / (s + EPSF);
}

// ---------------- performer scan, pass 1: per-chunk totals -------------------
__global__ void __launch_bounds__(64) perf_pass1()
{
    int bid = blockIdx.x;
    int c  = bid % CCH;
    int bh = bid / CCH;
    int h = bh % H_, b = bh / H_;
    int t = threadIdx.x;                       // dk lane
    float kv[M_], ks[M_];
    #pragma unroll
    for (int m = 0; m < M_; m++) { kv[m] = 0.f; ks[m] = 0.f; }
    int s0 = c*TCH;
    for (int s = s0; s < s0+TCH; s++) {
        size_t base = ((size_t)(b*S_+s)*H_ + h);
        float vt = g_v[base*DK_ + t];
        const float* kpp = &g_kp[base*M_];
        #pragma unroll
        for (int m = 0; m < M_; m++) { float kpv = kpp[m]; kv[m] += kpv*vt; ks[m] += kpv; }
    }
    size_t cb = ((size_t)bh*CCH + c)*M_;
    #pragma unroll
    for (int m = 0; m < M_; m++) g_ckv[(cb+m)*DK_ + t] = kv[m];
    if (t < M_) g_ck[cb + t] = ks[t];
}

// ---------------- performer scan, prefix over chunks (exclusive) -------------
__global__ void __launch_bounds__(64) perf_prefix()
{
    int bh = blockIdx.x;
    int t = threadIdx.x;
    for (int m = 0; m < M_; m++) {
        float vals[CCH];
        #pragma unroll
        for (int c = 0; c < CCH; c++)
            vals[c] = g_ckv[(((size_t)bh*CCH + c)*M_ + m)*DK_ + t];
        float acc = 0.f;
        #pragma unroll
        for (int c = 0; c < CCH; c++) { float tmp = vals[c]; vals[c] = acc; acc += tmp; }
        #pragma unroll
        for (int c = 0; c < CCH; c++)
            g_ckv[(((size_t)bh*CCH + c)*M_ + m)*DK_ + t] = vals[c];
    }
    if (t < M_) {
        float vals[CCH];
        #pragma unroll
        for (int c = 0; c < CCH; c++) vals[c] = g_ck[((size_t)bh*CCH + c)*M_ + t];
        float acc = 0.f;
        #pragma unroll
        for (int c = 0; c < CCH; c++) { float tmp = vals[c]; vals[c] = acc; acc += tmp; }
        #pragma unroll
        for (int c = 0; c < CCH; c++) g_ck[((size_t)bh*CCH + c)*M_ + t] = vals[c];
    }
}

// ---------------- performer scan, pass 2: replay + emit output ---------------
__global__ void __launch_bounds__(64) perf_pass2()
{
    int bid = blockIdx.x;
    int c  = bid % CCH;
    int bh = bid / CCH;
    int h = bh % H_, b = bh / H_;
    int t = threadIdx.x;
    float kv[M_], kc[M_];
    size_t cb = ((size_t)bh*CCH + c)*M_;
    #pragma unroll
    for (int m = 0; m < M_; m++) { kv[m] = g_ckv[(cb+m)*DK_ + t]; kc[m] = g_ck[cb+m]; }
    float gate = g_gate[bh];
    int s0 = c*TCH;
    for (int s = s0; s < s0+TCH; s++) {
        size_t base = ((size_t)(b*S_+s)*H_ + h);
        float vt = g_v[base*DK_ + t];
        const float* kpp = &g_kp[base*M_];
        const float* qpp = &g_qp[base*M_];
        float num = 0.f, den = 0.f;
        #pragma unroll
        for (int m = 0; m < M_; m++) {
            float kpv = kpp[m]; kv[m] += kpv*vt; kc[m] += kpv;
            float qpv = qpp[m]; num += qpv*kv[m]; den += qpv*kc[m];
        }
        g_att[base*DK_ + t] = num / (den + EPSF) * gate;
    }
}

// =============================================================================
extern "C" void kernel_launch(void* const* d_in, const int* in_sizes, int n_in,
                              void* d_out, int out_size)
{
    const int*   ids         = (const int*)  d_in[0];
    const int*   user_ids    = (const int*)  d_in[1];
    const float* id_embed    = (const float*)d_in[2];
    const float* feat_proj   = (const float*)d_in[3];
    const float* gamma       = (const float*)d_in[4];
    const float* gate_logits = (const float*)d_in[5];
    const float* wq          = (const float*)d_in[6];
    const float* wk          = (const float*)d_in[7];
    const float* wv          = (const float*)d_in[8];
    const float* wo          = (const float*)d_in[9];
    const float* omega       = (const float*)d_in[10];
    const float* ln1_a       = (const float*)d_in[11];
    const float* ln1_b       = (const float*)d_in[12];
    const float* ln2_a       = (const float*)d_in[13];
    const float* ln2_b       = (const float*)d_in[14];
    const float* ff_w1       = (const float*)d_in[15];
    const float* ff_b1       = (const float*)d_in[16];
    const float* ff_w2       = (const float*)d_in[17];
    const float* ff_b2       = (const float*)d_in[18];
    const float* fin_a       = (const float*)d_in[19];
    const float* fin_b       = (const float*)d_in[20];
    const float* proj_w      = (const float*)d_in[21];
    const float* proj_b      = (const float*)d_in[22];
    const float* feat_tbl    = (const float*)d_in[23];
    /* d_in[24] = prod_mask (derived from ids>=10 instead) */
    const float* pe          = (const float*)d_in[25];
    float* out = (float*)d_out;

    float *px, *pxn, *pq, *pk, *pv, *pqp, *pkp, *patt, *ph1;
    cudaGetSymbolAddress((void**)&px,   g_x);
    cudaGetSymbolAddress((void**)&pxn,  g_xn);
    cudaGetSymbolAddress((void**)&pq,   g_q);
    cudaGetSymbolAddress((void**)&pk,   g_k);
    cudaGetSymbolAddress((void**)&pv,   g_v);
    cudaGetSymbolAddress((void**)&pqp,  g_qp);
    cudaGetSymbolAddress((void**)&pkp,  g_kp);
    cudaGetSymbolAddress((void**)&patt, g_att);
    cudaGetSymbolAddress((void**)&ph1,  g_h1);

    embtbl_kernel<<<VS_, 256>>>(id_embed, feat_proj, gamma, feat_tbl);
    xinit_kernel<<<(BS_*D_ + 255)/256, 256>>>(ids, pe);
    gate_kernel<<<B_, 32>>>(user_ids, gate_logits);

    dim3 gDD(D_/128, BS_/128);        // (8, 32)
    dim3 gDF(DFF_/128, BS_/128);      // (32, 32)
    dim3 gVT((VT_+127)/128, BS_/128); // (1, 32)

    for (int l = 0; l < L_; l++) {
        const float* om = omega + (size_t)l*M_*DK_;
        ln_kernel<<<BS_, 256>>>(px, ln1_a + l*D_, ln1_b + l*D_, pxn);
        sgemm_nt<0><<<gDD, 256>>>(pxn, wq + (size_t)l*D_*D_, nullptr, nullptr, pq, BS_, D_, D_);
        sgemm_nt<0><<<gDD, 256>>>(pxn, wk + (size_t)l*D_*D_, nullptr, nullptr, pk, BS_, D_, D_);
        sgemm_nt<0><<<gDD, 256>>>(pxn, wv + (size_t)l*D_*D_, nullptr, nullptr, pv, BS_, D_, D_);
        featmap_kernel<<<BS_*H_/4, 128>>>(pq, om, pqp);
        featmap_kernel<<<BS_*H_/4, 128>>>(pk, om, pkp);
        perf_pass1<<<B_*H_*CCH, 64>>>();
        perf_prefix<<<B_*H_, 64>>>();
        perf_pass2<<<B_*H_*CCH, 64>>>();
        sgemm_nt<3><<<gDD, 256>>>(patt, wo + (size_t)l*D_*D_, nullptr, px, px, BS_, D_, D_);
        ln_kernel<<<BS_, 256>>>(px, ln2_a + l*D_, ln2_b + l*D_, pxn);
        sgemm_nt<2><<<gDF, 256>>>(pxn, ff_w1 + (size_t)l*DFF_*D_, ff_b1 + (size_t)l*DFF_,
                                  nullptr, ph1, BS_, DFF_, D_);
        sgemm_nt<4><<<gDD, 256>>>(ph1, ff_w2 + (size_t)l*D_*DFF_, ff_b2 + (size_t)l*D_,
                                  px, px, BS_, D_, DFF_);
    }

    ln_kernel<<<BS_, 256>>>(px, fin_a, fin_b, pxn);
    sgemm_nt<1><<<gVT, 256>>>(pxn, proj_w, proj_b, nullptr, out, BS_, VT_, D_);
}

// round 3
// speedup vs baseline: 1.8136x; 1.8136x over previous
#include <cuda_runtime.h>
#include <cuda_bf16.h>
#include <mma.h>
#include <math.h>

using namespace nvcuda;

#define B_   2
#define S_   2048
#define D_   1024
#define H_   16
#define DK_  64
#define M_   16
#define L_   4
#define DFF_ 4096
#define VT_  69
#define VS_  69
#define FD_  34
#define BS_  (B_*S_)
#define QS_  (3*D_)          // packed qkv row stride
#define CCH  32
#define TCH  64
#define EPSF 1e-6f

#define DD_       (D_*D_)                 // 1048576
#define OFF_QKV   ((size_t)0)             // L * 3 * DD
#define OFF_WO    ((size_t)12*DD_)        // L * DD
#define OFF_FF1   ((size_t)16*DD_)        // L * 4 * DD
#define OFF_FF2   ((size_t)32*DD_)        // L * 4 * DD
#define OFF_PROJ  ((size_t)48*DD_)        // VT_*D_
#define WTOT      (OFF_PROJ + (size_t)VT_*D_)

// ---------------- scratch (static device memory; no allocations) -------------
__device__ __align__(16) float g_emb2[VS_*D_];
__device__ __align__(16) float g_x   [BS_*D_];
__device__ __align__(16) __nv_bfloat16 g_xh[BS_*D_];
__device__ __align__(16) __nv_bfloat16 g_xl[BS_*D_];
__device__ __align__(16) float g_qkv [(size_t)BS_*QS_];
__device__ __align__(16) float g_qp  [BS_*H_*M_];
__device__ __align__(16) float g_kp  [BS_*H_*M_];
__device__ __align__(16) __nv_bfloat16 g_ah[BS_*D_];
__device__ __align__(16) __nv_bfloat16 g_al[BS_*D_];
__device__ __align__(16) __nv_bfloat16 g_h1h[(size_t)BS_*DFF_];
__device__ __align__(16) __nv_bfloat16 g_h1l[(size_t)BS_*DFF_];
__device__ __align__(16) __nv_bfloat16 g_wh[WTOT];
__device__ __align__(16) __nv_bfloat16 g_wl[WTOT];
__device__ __align__(16) float g_ckv[(size_t)B_*H_*CCH*M_*DK_];
__device__ __align__(16) float g_ck [B_*H_*CCH*M_];
__device__ float g_gate[B_*H_];

// ---------------- weight split: w -> (hi, lo) bf16 at packed offset ----------
__global__ void wsplit_kernel(const float* __restrict__ src, size_t n, size_t dstOff)
{
    for (size_t i = (size_t)blockIdx.x*blockDim.x + threadIdx.x; i < n;
         i += (size_t)gridDim.x*blockDim.x) {
        float v = src[i];
        __nv_bfloat16 h = __float2bfloat16(v);
        g_wh[dstOff+i] = h;
        g_wl[dstOff+i] = __float2bfloat16(v - __bfloat162float(h));
    }
}

// ---------------- fused embedding table --------------------------------------
__global__ void embtbl_kernel(const float* __restrict__ id_embed,
                              const float* __restrict__ feat_proj,
                              const float* __restrict__ gammap,
                              const float* __restrict__ feat_tbl)
{
    int v = blockIdx.x;
    float gscale = gammap[0] * ((v >= 10) ? 1.f : 0.f);
    __shared__ float ft[FD_];
    if (threadIdx.x < FD_) ft[threadIdx.x] = feat_tbl[v*FD_ + threadIdx.x];
    __syncthreads();
    for (int d = threadIdx.x; d < D_; d += blockDim.x) {
        float dot = 0.f;
        #pragma unroll
        for (int f = 0; f < FD_; f++) dot += ft[f] * feat_proj[d*FD_ + f];
        g_emb2[v*D_ + d] = id_embed[(size_t)v*D_ + d] + gscale * dot;
    }
}

__global__ void xinit_kernel(const int* __restrict__ ids, const float* __restrict__ pe)
{
    int idx = blockIdx.x*blockDim.x + threadIdx.x;
    if (idx >= BS_*D_) return;
    int d = idx % D_;
    int bs = idx / D_;
    int s = bs % S_;
    g_x[idx] = g_emb2[ids[bs]*D_ + d] + pe[(size_t)s*D_ + d];
}

__global__ void gate_kernel(const int* __restrict__ user_ids,
                            const float* __restrict__ gl)
{
    int b = blockIdx.x;
    int lane = threadIdx.x;
    float v = (lane < H_) ? gl[(size_t)user_ids[b]*H_ + lane] : -1e30f;
    float mx = v;
    #pragma unroll
    for (int o = 16; o > 0; o >>= 1) mx = fmaxf(mx, __shfl_xor_sync(~0u, mx, o));
    float e = (lane < H_) ? expf(v - mx) : 0.f;
    float s = e;
    #pragma unroll
    for (int o = 16; o > 0; o >>= 1) s += __shfl_xor_sync(~0u, s, o);
    if (lane < H_) g_gate[b*H_ + lane] = e / s;
}

// ---------------- LayerNorm -> bf16 hi/lo split ------------------------------
__global__ void __launch_bounds__(256) ln_kernel(const float* __restrict__ X,
                                                 const float* __restrict__ alpha,
                                                 const float* __restrict__ beta,
                                                 __nv_bfloat16* __restrict__ Yh,
                                                 __nv_bfloat16* __restrict__ Yl)
{
    int row = blockIdx.x;
    const float* x = X + (size_t)row*D_;
    float s = 0.f, s2 = 0.f;
    for (int d = threadIdx.x; d < D_; d += blockDim.x) {
        float v = x[d]; s += v; s2 += v*v;
    }
    __shared__ float red[64];
    #pragma unroll
    for (int o = 16; o > 0; o >>= 1) {
        s  += __shfl_down_sync(~0u, s,  o);
        s2 += __shfl_down_sync(~0u, s2, o);
    }
    int w = threadIdx.x >> 5, lane = threadIdx.x & 31;
    if (lane == 0) { red[w] = s; red[w+32] = s2; }
    __syncthreads();
    if (w == 0) {
        s  = (lane < 8) ? red[lane]    : 0.f;
        s2 = (lane < 8) ? red[lane+32] : 0.f;
        #pragma unroll
        for (int o = 4; o > 0; o >>= 1) {
            s  += __shfl_down_sync(~0u, s,  o);
            s2 += __shfl_down_sync(~0u, s2, o);
        }
        if (lane == 0) { red[0] = s; red[1] = s2; }
    }
    __syncthreads();
    float mu  = red[0] / (float)D_;
    float var = (red[1] - (float)D_*mu*mu) / (float)(D_-1);
    float inv = 1.f / (sqrtf(fmaxf(var, 0.f)) + EPSF);
    for (int d = threadIdx.x; d < D_; d += blockDim.x) {
        float vv = alpha[d] * (x[d] - mu) * inv + beta[d];
        __nv_bfloat16 h = __float2bfloat16(vv);
        Yh[(size_t)row*D_ + d] = h;
        Yl[(size_t)row*D_ + d] = __float2bfloat16(vv - __bfloat162float(h));
    }
}

// ---------------- split-bf16 tensor-core GEMM (NT): C = A*B^T -----------------
// A = Ah+Al [4096,K], B = Bh+Bl [Nc,K] row-major bf16 pairs; fp32 accumulate.
// EPI: 0 plain fp32; 1 bias fp32 (col-guarded); 2 bias+gelu -> bf16 split;
//      3 +residual fp32; 4 bias+residual fp32
template<int EPI>
__global__ void __launch_bounds__(256, 2) bgemm(
    const __nv_bfloat16* __restrict__ Ah, const __nv_bfloat16* __restrict__ Al,
    const __nv_bfloat16* __restrict__ Bh, const __nv_bfloat16* __restrict__ Bl,
    const float* __restrict__ bias, const float* __restrict__ res,
    float* __restrict__ Cf, __nv_bfloat16* __restrict__ Ch, __nv_bfloat16* __restrict__ Cl,
    int Nc, int K)
{
    __shared__ __align__(16) unsigned char smem_raw[49152];
    const int tid = threadIdx.x;
    const int warpId = tid >> 5;
    const int warp_m = warpId & 3;          // 4 warps along M (32 rows each)
    const int warp_n = warpId >> 2;         // 2 warps along N (64 cols each)
    const int m0 = blockIdx.y * 128;
    const int n0 = blockIdx.x * 128;

    wmma::fragment<wmma::accumulator,16,16,16,float> c[2][4];
    #pragma unroll
    for (int i = 0; i < 2; i++)
        #pragma unroll
        for (int j = 0; j < 4; j++) wmma::fill_fragment(c[i][j], 0.f);

    const int row  = tid >> 1;              // 0..127
    const int half = tid & 1;               // 16B half of 32B row

    // stage buf layout (bytes): Ah@0  Al@6144  Bh@12288  Bl@18432 ; stage stride 24576
    auto loadChunk = [&](int kc, int buf) {
        const int k0 = kc * 16;
        size_t aoff = (size_t)(m0 + row)*K + k0 + half*8;
        int brow = n0 + row;
        int bp = (brow < Nc) ? 16 : 0;
        size_t boff = (size_t)(bp ? brow : 0)*K + k0 + half*8;
        unsigned dst = (unsigned)__cvta_generic_to_shared(
            smem_raw + buf*24576 + (row*24 + half*8)*2);
        asm volatile("cp.async.cg.shared.global [%0], [%1], 16;\n"
                     :: "r"(dst),         "l"(Ah + aoff));
        asm volatile("cp.async.cg.shared.global [%0], [%1], 16;\n"
                     :: "r"(dst +  6144), "l"(Al + aoff));
        asm volatile("cp.async.cg.shared.global [%0], [%1], 16, %2;\n"
                     :: "r"(dst + 12288), "l"(Bh + boff), "r"(bp));
        asm volatile("cp.async.cg.shared.global [%0], [%1], 16, %2;\n"
                     :: "r"(dst + 18432), "l"(Bl + boff), "r"(bp));
    };

    const int nch = K >> 4;
    loadChunk(0, 0);
    asm volatile("cp.async.commit_group;\n");

    for (int kc = 0; kc < nch; kc++) {
        if (kc + 1 < nch) {
            loadChunk(kc + 1, (kc + 1) & 1);
            asm volatile("cp.async.commit_group;\n");
            asm volatile("cp.async.wait_group 1;\n");
        } else {
            asm volatile("cp.async.wait_group 0;\n");
        }
        __syncthreads();
        const __nv_bfloat16* sAh = (const __nv_bfloat16*)(smem_raw + (kc & 1)*24576);
        const __nv_bfloat16* sAl = sAh + 3072;
        const __nv_bfloat16* sBh = sAh + 6144;
        const __nv_bfloat16* sBl = sAh + 9216;

        wmma::fragment<wmma::matrix_a,16,16,16,__nv_bfloat16,wmma::row_major> afh[2], afl[2];
        #pragma unroll
        for (int mi = 0; mi < 2; mi++) {
            int r0 = warp_m*32 + mi*16;
            wmma::load_matrix_sync(afh[mi], sAh + r0*24, 24);
            wmma::load_matrix_sync(afl[mi], sAl + r0*24, 24);
        }
        #pragma unroll
        for (int ni = 0; ni < 4; ni++) {
            int rn = warp_n*64 + ni*16;
            wmma::fragment<wmma::matrix_b,16,16,16,__nv_bfloat16,wmma::col_major> bfh, bfl;
            wmma::load_matrix_sync(bfh, sBh + rn*24, 24);
            wmma::load_matrix_sync(bfl, sBl + rn*24, 24);
            #pragma unroll
            for (int mi = 0; mi < 2; mi++) {
                wmma::mma_sync(c[mi][ni], afh[mi], bfh, c[mi][ni]);
                wmma::mma_sync(c[mi][ni], afl[mi], bfh, c[mi][ni]);
                wmma::mma_sync(c[mi][ni], afh[mi], bfl, c[mi][ni]);
            }
        }
        __syncthreads();
    }

    // epilogue: stage 128x64 halves in smem, then coalesced elementwise
    float* stage = (float*)smem_raw;   // [128][68]
    #pragma unroll
    for (int p = 0; p < 2; p++) {
        if (warp_n == p) {
            #pragma unroll
            for (int mi = 0; mi < 2; mi++)
                #pragma unroll
                for (int ni = 0; ni < 4; ni++)
                    wmma::store_matrix_sync(stage + (warp_m*32 + mi*16)*68 + ni*16,
                                            c[mi][ni], 68, wmma::mem_row_major);
        }
        __syncthreads();
        for (int e = tid; e < 8192; e += 256) {
            int r  = e >> 6, cc = e & 63;
            int col = n0 + p*64 + cc;
            size_t gi = (size_t)(m0 + r)*Nc + col;
            float v = stage[r*68 + cc];
            if (EPI == 1) {
                if (col < Nc) { Cf[(size_t)(m0 + r)*Nc + col] = v + bias[col]; }
            } else if (EPI == 2) {
                v += bias[col];
                float xg = v;
                v = 0.5f*xg*(1.f + tanhf(0.7978845608028654f*(xg + 0.044715f*xg*xg*xg)));
                __nv_bfloat16 h = __float2bfloat16(v);
                Ch[gi] = h;
                Cl[gi] = __float2bfloat16(v - __bfloat162float(h));
            } else if (EPI == 3) {
                Cf[gi] = v + res[gi];
            } else if (EPI == 4) {
                Cf[gi] = v + bias[col] + res[gi];
            } else {
                Cf[gi] = v;
            }
        }
        __syncthreads();
    }
}

// ---------------- feature map (reads packed qkv fp32) ------------------------
__global__ void __launch_bounds__(128) featmap_kernel(
    const float* __restrict__ Q, const float* __restrict__ omega,
    float* __restrict__ P)
{
    int wl = threadIdx.x >> 5;
    int lane = threadIdx.x & 31;
    int gw = blockIdx.x*4 + wl;                 // token-head index
    int h  = gw % H_;
    int bs = gw / H_;
    const float* q = Q + (size_t)bs*QS_ + h*DK_;
    __shared__ float sq[4][DK_];
    sq[wl][lane]    = q[lane];
    sq[wl][lane+32] = q[lane+32];
    __syncwarp();
    float t = 0.f;
    if (lane < M_) {
        float dot = 0.f;
        #pragma unroll
        for (int d = 0; d < DK_; d++) dot += sq[wl][d]*omega[lane*DK_ + d];
        t = expf(-0.5f*dot*dot);
    }
    float s = t;
    #pragma unroll
    for (int o = 16; o > 0; o >>= 1) s += __shfl_xor_sync(~0u, s, o);
    if (lane < M_) P[(size_t)gw*M_ + lane] = t / (s + EPSF);
}

// ---------------- performer scan --------------------------------------------
__global__ void __launch_bounds__(64) perf_pass1()
{
    int bid = blockIdx.x;
    int c  = bid % CCH;
    int bh = bid / CCH;
    int h = bh % H_, b = bh / H_;
    int t = threadIdx.x;
    float kv[M_], ks[M_];
    #pragma unroll
    for (int m = 0; m < M_; m++) { kv[m] = 0.f; ks[m] = 0.f; }
    int s0 = c*TCH;
    for (int s = s0; s < s0+TCH; s++) {
        size_t tok = (size_t)(b*S_+s);
        float vt = g_qkv[tok*QS_ + 2*D_ + h*DK_ + t];
        const float* kpp = &g_kp[(tok*H_ + h)*M_];
        #pragma unroll
        for (int m = 0; m < M_; m++) { float kpv = kpp[m]; kv[m] += kpv*vt; ks[m] += kpv; }
    }
    size_t cb = ((size_t)bh*CCH + c)*M_;
    #pragma unroll
    for (int m = 0; m < M_; m++) g_ckv[(cb+m)*DK_ + t] = kv[m];
    if (t < M_) g_ck[cb + t] = ks[t];
}

__global__ void __launch_bounds__(64) perf_prefix()
{
    int bh = blockIdx.x;
    int t = threadIdx.x;
    for (int m = 0; m < M_; m++) {
        float vals[CCH];
        #pragma unroll
        for (int c = 0; c < CCH; c++)
            vals[c] = g_ckv[(((size_t)bh*CCH + c)*M_ + m)*DK_ + t];
        float acc = 0.f;
        #pragma unroll
        for (int c = 0; c < CCH; c++) { float tmp = vals[c]; vals[c] = acc; acc += tmp; }
        #pragma unroll
        for (int c = 0; c < CCH; c++)
            g_ckv[(((size_t)bh*CCH + c)*M_ + m)*DK_ + t] = vals[c];
    }
    if (t < M_) {
        float vals[CCH];
        #pragma unroll
        for (int c = 0; c < CCH; c++) vals[c] = g_ck[((size_t)bh*CCH + c)*M_ + t];
        float acc = 0.f;
        #pragma unroll
        for (int c = 0; c < CCH; c++) { float tmp = vals[c]; vals[c] = acc; acc += tmp; }
        #pragma unroll
        for (int c = 0; c < CCH; c++) g_ck[((size_t)bh*CCH + c)*M_ + t] = vals[c];
    }
}

__global__ void __launch_bounds__(64) perf_pass2()
{
    int bid = blockIdx.x;
    int c  = bid % CCH;
    int bh = bid / CCH;
    int h = bh % H_, b = bh / H_;
    int t = threadIdx.x;
    float kv[M_], kc[M_];
    size_t cb = ((size_t)bh*CCH + c)*M_;
    #pragma unroll
    for (int m = 0; m < M_; m++) { kv[m] = g_ckv[(cb+m)*DK_ + t]; kc[m] = g_ck[cb+m]; }
    float gate = g_gate[bh];
    int s0 = c*TCH;
    for (int s = s0; s < s0+TCH; s++) {
        size_t tok = (size_t)(b*S_+s);
        float vt = g_qkv[tok*QS_ + 2*D_ + h*DK_ + t];
        const float* kpp = &g_kp[(tok*H_ + h)*M_];
        const float* qpp = &g_qp[(tok*H_ + h)*M_];
        float num = 0.f, den = 0.f;
        #pragma unroll
        for (int m = 0; m < M_; m++) {
            float kpv = kpp[m]; kv[m] += kpv*vt; kc[m] += kpv;
            float qpv = qpp[m]; num += qpv*kv[m]; den += qpv*kc[m];
        }
        float o = num / (den + EPSF) * gate;
        size_t oi = tok*D_ + h*DK_ + t;
        __nv_bfloat16 hh = __float2bfloat16(o);
        g_ah[oi] = hh;
        g_al[oi] = __float2bfloat16(o - __bfloat162float(hh));
    }
}

// =============================================================================
extern "C" void kernel_launch(void* const* d_in, const int* in_sizes, int n_in,
                              void* d_out, int out_size)
{
    const int*   ids         = (const int*)  d_in[0];
    const int*   user_ids    = (const int*)  d_in[1];
    const float* id_embed    = (const float*)d_in[2];
    const float* feat_proj   = (const float*)d_in[3];
    const float* gamma       = (const float*)d_in[4];
    const float* gate_logits = (const float*)d_in[5];
    const float* wq          = (const float*)d_in[6];
    const float* wk          = (const float*)d_in[7];
    const float* wv          = (const float*)d_in[8];
    const float* wo          = (const float*)d_in[9];
    const float* omega       = (const float*)d_in[10];
    const float* ln1_a       = (const float*)d_in[11];
    const float* ln1_b       = (const float*)d_in[12];
    const float* ln2_a       = (const float*)d_in[13];
    const float* ln2_b       = (const float*)d_in[14];
    const float* ff_w1       = (const float*)d_in[15];
    const float* ff_b1       = (const float*)d_in[16];
    const float* ff_w2       = (const float*)d_in[17];
    const float* ff_b2       = (const float*)d_in[18];
    const float* fin_a       = (const float*)d_in[19];
    const float* fin_b       = (const float*)d_in[20];
    const float* proj_w      = (const float*)d_in[21];
    const float* proj_b      = (const float*)d_in[22];
    const float* feat_tbl    = (const float*)d_in[23];
    /* d_in[24] = prod_mask (derived as ids>=10) */
    const float* pe          = (const float*)d_in[25];
    float* out = (float*)d_out;

    float *px, *pqkv, *pqp, *pkp;
    __nv_bfloat16 *pxh, *pxl, *pah, *pal, *ph1h, *ph1l, *pwh, *pwl;
    cudaGetSymbolAddress((void**)&px,   g_x);
    cudaGetSymbolAddress((void**)&pxh,  g_xh);
    cudaGetSymbolAddress((void**)&pxl,  g_xl);
    cudaGetSymbolAddress((void**)&pqkv, g_qkv);
    cudaGetSymbolAddress((void**)&pqp,  g_qp);
    cudaGetSymbolAddress((void**)&pkp,  g_kp);
    cudaGetSymbolAddress((void**)&pah,  g_ah);
    cudaGetSymbolAddress((void**)&pal,  g_al);
    cudaGetSymbolAddress((void**)&ph1h, g_h1h);
    cudaGetSymbolAddress((void**)&ph1l, g_h1l);
    cudaGetSymbolAddress((void**)&pwh,  g_wh);
    cudaGetSymbolAddress((void**)&pwl,  g_wl);

    embtbl_kernel<<<VS_, 256>>>(id_embed, feat_proj, gamma, feat_tbl);
    xinit_kernel<<<(BS_*D_ + 255)/256, 256>>>(ids, pe);
    gate_kernel<<<B_, 32>>>(user_ids, gate_logits);

    // weight splits into packed bf16 hi/lo
    for (int l = 0; l < L_; l++) {
        wsplit_kernel<<<1024, 256>>>(wq + (size_t)l*DD_, DD_, OFF_QKV + (size_t)l*3*DD_);
        wsplit_kernel<<<1024, 256>>>(wk + (size_t)l*DD_, DD_, OFF_QKV + (size_t)l*3*DD_ + DD_);
        wsplit_kernel<<<1024, 256>>>(wv + (size_t)l*DD_, DD_, OFF_QKV + (size_t)l*3*DD_ + 2*DD_);
    }
    wsplit_kernel<<<2048, 256>>>(wo,     (size_t)4*DD_,  OFF_WO);
    wsplit_kernel<<<4096, 256>>>(ff_w1,  (size_t)16*DD_, OFF_FF1);
    wsplit_kernel<<<4096, 256>>>(ff_w2,  (size_t)16*DD_, OFF_FF2);
    wsplit_kernel<<<256,  256>>>(proj_w, (size_t)VT_*D_, OFF_PROJ);

    dim3 gQKV(24, 32);   // N=3072
    dim3 gDD (8, 32);    // N=1024
    dim3 gDF (32, 32);   // N=4096
    dim3 gVT (1, 32);    // N=69 (padded to 128)

    for (int l = 0; l < L_; l++) {
        const float* om = omega + (size_t)l*M_*DK_;
        ln_kernel<<<BS_, 256>>>(px, ln1_a + l*D_, ln1_b + l*D_, pxh, pxl);
        bgemm<0><<<gQKV, 256>>>(pxh, pxl,
                                pwh + OFF_QKV + (size_t)l*3*DD_, pwl + OFF_QKV + (size_t)l*3*DD_,
                                nullptr, nullptr, pqkv, nullptr, nullptr, QS_, D_);
        featmap_kernel<<<BS_*H_/4, 128>>>(pqkv,        om, pqp);
        featmap_kernel<<<BS_*H_/4, 128>>>(pqkv + D_,   om, pkp);
        perf_pass1<<<B_*H_*CCH, 64>>>();
        perf_prefix<<<B_*H_, 64>>>();
        perf_pass2<<<B_*H_*CCH, 64>>>();
        bgemm<3><<<gDD, 256>>>(pah, pal,
                               pwh + OFF_WO + (size_t)l*DD_, pwl + OFF_WO + (size_t)l*DD_,
                               nullptr, px, px, nullptr, nullptr, D_, D_);
        ln_kernel<<<BS_, 256>>>(px, ln2_a + l*D_, ln2_b + l*D_, pxh, pxl);
        bgemm<2><<<gDF, 256>>>(pxh, pxl,
                               pwh + OFF_FF1 + (size_t)l*4*DD_, pwl + OFF_FF1 + (size_t)l*4*DD_,
                               ff_b1 + (size_t)l*DFF_, nullptr, nullptr, ph1h, ph1l, DFF_, D_);
        bgemm<4><<<gDD, 256>>>(ph1h, ph1l,
                               pwh + OFF_FF2 + (size_t)l*4*DD_, pwl + OFF_FF2 + (size_t)l*4*DD_,
                               ff_b2 + (size_t)l*D_, px, px, nullptr, nullptr, D_, DFF_);
    }

    ln_kernel<<<BS_, 256>>>(px, fin_a, fin_b, pxh, pxl);
    bgemm<1><<<gVT, 256>>>(pxh, pxl, pwh + OFF_PROJ, pwl + OFF_PROJ,
                           proj_b, nullptr, out, nullptr, nullptr, VT_, D_);
}

// round 6
// speedup vs baseline: 2.6078x; 1.4379x over previous
#include <cuda_runtime.h>
#include <cuda_bf16.h>
#include <mma.h>
#include <math.h>
#include <stdint.h>

using namespace nvcuda;

#define B_   2
#define S_   2048
#define D_   1024
#define H_   16
#define DK_  64
#define M_   16
#define L_   4
#define DFF_ 4096
#define VT_  69
#define VS_  69
#define FD_  34
#define BS_  (B_*S_)
#define QS2_ 1536            // packed [qfeat 256 | kfeat 256 | v 1024]
#define VOFF 512
#define CCH  32
#define TCH  64
#define EPSF 1e-6f

#define DD_       ((size_t)D_*D_)
#define R_QKV     ((size_t)QS2_*D_)                  // per-layer qkv-panel rows
#define OFF_QKV   ((size_t)0)                        // L * R_QKV
#define OFF_WO    ((size_t)L_*R_QKV)
#define OFF_FF1   (OFF_WO  + (size_t)L_*DD_)
#define OFF_FF2   (OFF_FF1 + (size_t)L_*4*DD_)
#define OFF_PROJ  (OFF_FF2 + (size_t)L_*4*DD_)
#define WTOT      (OFF_PROJ + (size_t)VT_*D_)

// ---------------- scratch ----------------------------------------------------
__device__ __align__(16) float g_emb2[VS_*D_];
__device__ __align__(16) float g_x   [BS_*D_];
__device__ __align__(16) __nv_bfloat16 g_xh[BS_*D_];
__device__ __align__(16) __nv_bfloat16 g_xl[BS_*D_];
__device__ __align__(16) float g_qkv [(size_t)BS_*QS2_];
__device__ __align__(16) float g_qp  [BS_*H_*M_];
__device__ __align__(16) float g_kp  [BS_*H_*M_];
__device__ __align__(16) __nv_bfloat16 g_ah[BS_*D_];
__device__ __align__(16) __nv_bfloat16 g_al[BS_*D_];
__device__ __align__(16) __nv_bfloat16 g_h1h[(size_t)BS_*DFF_];
__device__ __align__(16) __nv_bfloat16 g_h1l[(size_t)BS_*DFF_];
__device__ __align__(16) __nv_bfloat16 g_wh[WTOT];
__device__ __align__(16) __nv_bfloat16 g_wl[WTOT];
__device__ __align__(16) float g_ckv[(size_t)B_*H_*CCH*M_*DK_];
__device__ __align__(16) float g_ck [B_*H_*CCH*M_];
__device__ float g_gate[B_*H_];

// ---------------- vectorized weight split ------------------------------------
__global__ void wsplit_kernel(const float4* __restrict__ src, size_t n4, size_t dstOff)
{
    __nv_bfloat162* wh2 = (__nv_bfloat162*)(g_wh + dstOff);
    __nv_bfloat162* wl2 = (__nv_bfloat162*)(g_wl + dstOff);
    for (size_t i = (size_t)blockIdx.x*blockDim.x + threadIdx.x; i < n4;
         i += (size_t)gridDim.x*blockDim.x) {
        float4 v = src[i];
        __nv_bfloat16 hx = __float2bfloat16(v.x), hy = __float2bfloat16(v.y);
        __nv_bfloat16 hz = __float2bfloat16(v.z), hw = __float2bfloat16(v.w);
        wh2[i*2]   = __halves2bfloat162(hx, hy);
        wh2[i*2+1] = __halves2bfloat162(hz, hw);
        wl2[i*2]   = __halves2bfloat162(__float2bfloat16(v.x - __bfloat162float(hx)),
                                        __float2bfloat16(v.y - __bfloat162float(hy)));
        wl2[i*2+1] = __halves2bfloat162(__float2bfloat16(v.z - __bfloat162float(hz)),
                                        __float2bfloat16(v.w - __bfloat162float(hw)));
    }
}

// ---------------- fold omega into wq/wk:  out[(h,m), d] = sum_dk om[m,dk]*w[h*64+dk, d]
__global__ void __launch_bounds__(256) featfold_kernel(
    const float* __restrict__ w, const float* __restrict__ om, size_t dstRowBase)
{
    int h = blockIdx.x;
    int tid = threadIdx.x;
    __shared__ float so[M_][DK_];
    for (int i = tid; i < M_*DK_; i += 256) so[i/DK_][i%DK_] = om[i];
    __syncthreads();
    for (int db = 0; db < D_/256; db++) {
        int d = db*256 + tid;
        float acc[M_];
        #pragma unroll
        for (int m = 0; m < M_; m++) acc[m] = 0.f;
        for (int dk = 0; dk < DK_; dk++) {
            float wv = w[(size_t)(h*DK_+dk)*D_ + d];
            #pragma unroll
            for (int m = 0; m < M_; m++) acc[m] += so[m][dk]*wv;
        }
        #pragma unroll
        for (int m = 0; m < M_; m++) {
            float v = acc[m];
            __nv_bfloat16 hh = __float2bfloat16(v);
            size_t oi = dstRowBase + (size_t)(h*M_+m)*D_ + d;
            g_wh[oi] = hh;
            g_wl[oi] = __float2bfloat16(v - __bfloat162float(hh));
        }
    }
}

// ---------------- embedding / init / gate ------------------------------------
__global__ void embtbl_kernel(const float* __restrict__ id_embed,
                              const float* __restrict__ feat_proj,
                              const float* __restrict__ gammap,
                              const float* __restrict__ feat_tbl)
{
    int v = blockIdx.x;
    float gscale = gammap[0] * ((v >= 10) ? 1.f : 0.f);
    __shared__ float ft[FD_];
    if (threadIdx.x < FD_) ft[threadIdx.x] = feat_tbl[v*FD_ + threadIdx.x];
    __syncthreads();
    for (int d = threadIdx.x; d < D_; d += blockDim.x) {
        float dot = 0.f;
        #pragma unroll
        for (int f = 0; f < FD_; f++) dot += ft[f] * feat_proj[d*FD_ + f];
        g_emb2[v*D_ + d] = id_embed[(size_t)v*D_ + d] + gscale * dot;
    }
}

__global__ void xinit_kernel(const int* __restrict__ ids, const float* __restrict__ pe)
{
    int idx = blockIdx.x*blockDim.x + threadIdx.x;
    if (idx >= BS_*D_) return;
    int d = idx % D_;
    int bs = idx / D_;
    int s = bs % S_;
    g_x[idx] = g_emb2[ids[bs]*D_ + d] + pe[(size_t)s*D_ + d];
}

__global__ void gate_kernel(const int* __restrict__ user_ids,
                            const float* __restrict__ gl)
{
    int b = blockIdx.x;
    int lane = threadIdx.x;
    float v = (lane < H_) ? gl[(size_t)user_ids[b]*H_ + lane] : -1e30f;
    float mx = v;
    #pragma unroll
    for (int o = 16; o > 0; o >>= 1) mx = fmaxf(mx, __shfl_xor_sync(~0u, mx, o));
    float e = (lane < H_) ? expf(v - mx) : 0.f;
    float s = e;
    #pragma unroll
    for (int o = 16; o > 0; o >>= 1) s += __shfl_xor_sync(~0u, s, o);
    if (lane < H_) g_gate[b*H_ + lane] = e / s;
}

// ---------------- LayerNorm -> bf16 hi/lo ------------------------------------
__global__ void __launch_bounds__(256) ln_kernel(const float* __restrict__ X,
                                                 const float* __restrict__ alpha,
                                                 const float* __restrict__ beta,
                                                 __nv_bfloat16* __restrict__ Yh,
                                                 __nv_bfloat16* __restrict__ Yl)
{
    int row = blockIdx.x;
    const float* x = X + (size_t)row*D_;
    float s = 0.f, s2 = 0.f;
    for (int d = threadIdx.x; d < D_; d += blockDim.x) {
        float v = x[d]; s += v; s2 += v*v;
    }
    __shared__ float red[64];
    #pragma unroll
    for (int o = 16; o > 0; o >>= 1) {
        s  += __shfl_down_sync(~0u, s,  o);
        s2 += __shfl_down_sync(~0u, s2, o);
    }
    int w = threadIdx.x >> 5, lane = threadIdx.x & 31;
    if (lane == 0) { red[w] = s; red[w+32] = s2; }
    __syncthreads();
    if (w == 0) {
        s  = (lane < 8) ? red[lane]    : 0.f;
        s2 = (lane < 8) ? red[lane+32] : 0.f;
        #pragma unroll
        for (int o = 4; o > 0; o >>= 1) {
            s  += __shfl_down_sync(~0u, s,  o);
            s2 += __shfl_down_sync(~0u, s2, o);
        }
        if (lane == 0) { red[0] = s; red[1] = s2; }
    }
    __syncthreads();
    float mu  = red[0] / (float)D_;
    float var = (red[1] - (float)D_*mu*mu) / (float)(D_-1);
    float inv = 1.f / (sqrtf(fmaxf(var, 0.f)) + EPSF);
    for (int d = threadIdx.x; d < D_; d += blockDim.x) {
        float vv = alpha[d] * (x[d] - mu) * inv + beta[d];
        __nv_bfloat16 h = __float2bfloat16(vv);
        Yh[(size_t)row*D_ + d] = h;
        Yl[(size_t)row*D_ + d] = __float2bfloat16(vv - __bfloat162float(h));
    }
}

// =============================================================================
//            mma.sync split-bf16 GEMM  (C = A * B^T), CTA 128x128
// k-chunk 16, 2-stage cp.async, ldmatrix operands, padded 48B smem rows.
// EPI: 0 plain fp32; 2 bias+gelu -> bf16 split; 3 +residual; 4 bias+residual
// =============================================================================
#define STG_BYTES 24576            // per stage: Ah 6144 | Al 6144 | Bh 6144 | Bl 6144
#define ROWB      48               // 24 bf16 per row (16 data + 8 pad)

static __device__ __forceinline__ void cpa16s(uint32_t dst, const void* src) {
    asm volatile("cp.async.cg.shared.global [%0], [%1], 16;" :: "r"(dst), "l"(src));
}
static __device__ __forceinline__ void ldm4(uint32_t* d, uint32_t a) {
    asm volatile("ldmatrix.sync.aligned.m8n8.x4.shared.b16 {%0,%1,%2,%3}, [%4];"
                 : "=r"(d[0]), "=r"(d[1]), "=r"(d[2]), "=r"(d[3]) : "r"(a));
}
static __device__ __forceinline__ void mma16816(float* c, const uint32_t* a, const uint32_t* b) {
    asm volatile("mma.sync.aligned.m16n8k16.row.col.f32.bf16.bf16.f32 "
                 "{%0,%1,%2,%3},{%4,%5,%6,%7},{%8,%9},{%0,%1,%2,%3};"
                 : "+f"(c[0]), "+f"(c[1]), "+f"(c[2]), "+f"(c[3])
                 : "r"(a[0]), "r"(a[1]), "r"(a[2]), "r"(a[3]), "r"(b[0]), "r"(b[1]));
}

template<int EPI>
__global__ void __launch_bounds__(256, 2) tgemm(
    const __nv_bfloat16* __restrict__ Ah, const __nv_bfloat16* __restrict__ Al,
    const __nv_bfloat16* __restrict__ Bh, const __nv_bfloat16* __restrict__ Bl,
    const float* __restrict__ bias, const float* __restrict__ res,
    float* __restrict__ Cf, __nv_bfloat16* __restrict__ Ch, __nv_bfloat16* __restrict__ Cl,
    int Nc, int K)
{
    __shared__ __align__(16) unsigned char sm[2*STG_BYTES];
    const uint32_t smB = (uint32_t)__cvta_generic_to_shared(sm);

    const int tid  = threadIdx.x;
    const int wid  = tid >> 5;
    const int lane = tid & 31;
    const int wm   = wid >> 1;            // 0..3  (32 rows each)
    const int wn   = wid & 1;             // 0..1  (64 cols each)
    const int m0 = blockIdx.y * 128;
    const int n0 = blockIdx.x * 128;

    float acc[2][8][4];
    #pragma unroll
    for (int i = 0; i < 2; i++)
        #pragma unroll
        for (int j = 0; j < 8; j++)
            #pragma unroll
            for (int q = 0; q < 4; q++) acc[i][j][q] = 0.f;

    // cp.async addressing: thread -> (row = tid>>1, q = tid&1)
    const int crow = tid >> 1, cq = tid & 1;
    const uint32_t cdst = (uint32_t)(crow*ROWB + cq*16);
    const size_t  asrc = (size_t)(m0 + crow)*K + cq*8;
    const size_t  bsrc = (size_t)(n0 + crow)*K + cq*8;

    // ldmatrix addressing (bytes within a 6144B region)
    const uint32_t aoff = (uint32_t)((wm*32 + (lane & 15))*ROWB + (lane >> 4)*16);
    const uint32_t boff = (uint32_t)((wn*64 + ((lane >> 4) << 3) + (lane & 7))*ROWB
                                     + ((lane >> 3) & 1)*16);

    auto loadChunk = [&](int c, int buf) {
        uint32_t bb = smB + buf*STG_BYTES + cdst;
        int k0 = c*16;
        cpa16s(bb,         Ah + asrc + k0);
        cpa16s(bb +  6144, Al + asrc + k0);
        cpa16s(bb + 12288, Bh + bsrc + k0);
        cpa16s(bb + 18432, Bl + bsrc + k0);
        asm volatile("cp.async.commit_group;");
    };

    const int nch = K >> 4;
    loadChunk(0, 0);

    for (int c = 0; c < nch; c++) {
        if (c + 1 < nch) {
            loadChunk(c + 1, (c + 1) & 1);
            asm volatile("cp.async.wait_group 1;");
        } else {
            asm volatile("cp.async.wait_group 0;");
        }
        __syncthreads();
        uint32_t bb = smB + (c & 1)*STG_BYTES;

        uint32_t aH[2][4], aL[2][4];
        ldm4(aH[0], bb + aoff);
        ldm4(aH[1], bb + aoff + 16*ROWB);
        ldm4(aL[0], bb + 6144 + aoff);
        ldm4(aL[1], bb + 6144 + aoff + 16*ROWB);

        #pragma unroll
        for (int half = 0; half < 2; half++) {
            uint32_t bH[2][4], bL[2][4];
            uint32_t bo = boff + half*32*ROWB;
            ldm4(bH[0], bb + 12288 + bo);
            ldm4(bH[1], bb + 12288 + bo + 16*ROWB);
            ldm4(bL[0], bb + 18432 + bo);
            ldm4(bL[1], bb + 18432 + bo + 16*ROWB);
            #pragma unroll
            for (int t = 0; t < 4; t++) {
                int nj = half*4 + t;
                const uint32_t* bh = &bH[t >> 1][(t & 1)*2];
                const uint32_t* bl = &bL[t >> 1][(t & 1)*2];
                #pragma unroll
                for (int mi = 0; mi < 2; mi++) {
                    mma16816(acc[mi][nj], aH[mi], bh);
                    mma16816(acc[mi][nj], aL[mi], bh);
                    mma16816(acc[mi][nj], aH[mi], bl);
                }
            }
        }
        __syncthreads();
    }

    // ---------------- epilogue: direct from fragments ------------------------
    const int gq = lane >> 2;             // group row 0..7
    const int qp = lane & 3;              // col pair
    #pragma unroll
    for (int mi = 0; mi < 2; mi++) {
        #pragma unroll
        for (int nj = 0; nj < 8; nj++) {
            int r0 = m0 + wm*32 + mi*16 + gq;
            int cc = n0 + wn*64 + nj*8 + qp*2;
            #pragma unroll
            for (int hrow = 0; hrow < 2; hrow++) {
                int rr = r0 + hrow*8;
                float v0 = acc[mi][nj][hrow*2 + 0];
                float v1 = acc[mi][nj][hrow*2 + 1];
                size_t gi = (size_t)rr*Nc + cc;
                if (EPI == 2) {
                    v0 += bias[cc]; v1 += bias[cc+1];
                    float x0 = v0, x1 = v1;
                    v0 = 0.5f*x0*(1.f + tanhf(0.7978845608028654f*(x0 + 0.044715f*x0*x0*x0)));
                    v1 = 0.5f*x1*(1.f + tanhf(0.7978845608028654f*(x1 + 0.044715f*x1*x1*x1)));
                    __nv_bfloat16 h0 = __float2bfloat16(v0), h1 = __float2bfloat16(v1);
                    *(__nv_bfloat162*)(Ch + gi) = __halves2bfloat162(h0, h1);
                    *(__nv_bfloat162*)(Cl + gi) = __halves2bfloat162(
                        __float2bfloat16(v0 - __bfloat162float(h0)),
                        __float2bfloat16(v1 - __bfloat162float(h1)));
                } else {
                    if (EPI == 3) { float2 r = *(const float2*)(res + gi); v0 += r.x; v1 += r.y; }
                    if (EPI == 4) {
                        float2 r = *(const float2*)(res + gi);
                        v0 += bias[cc] + r.x; v1 += bias[cc+1] + r.y;
                    }
                    *(float2*)(Cf + gi) = make_float2(v0, v1);
                }
            }
        }
    }
}

// ---------------- wmma GEMM for the tiny VT=69 projection --------------------
__global__ void __launch_bounds__(256, 2) bgemm_proj(
    const __nv_bfloat16* __restrict__ Ah, const __nv_bfloat16* __restrict__ Al,
    const __nv_bfloat16* __restrict__ Bh, const __nv_bfloat16* __restrict__ Bl,
    const float* __restrict__ bias, float* __restrict__ Cf, int Nc, int K)
{
    __shared__ __align__(16) unsigned char smem_raw[49152];
    const int tid = threadIdx.x;
    const int warpId = tid >> 5;
    const int warp_m = warpId & 3;
    const int warp_n = warpId >> 2;
    const int m0 = blockIdx.y * 128;
    const int n0 = blockIdx.x * 128;

    wmma::fragment<wmma::accumulator,16,16,16,float> c[2][4];
    #pragma unroll
    for (int i = 0; i < 2; i++)
        #pragma unroll
        for (int j = 0; j < 4; j++) wmma::fill_fragment(c[i][j], 0.f);

    const int row  = tid >> 1;
    const int half = tid & 1;

    auto loadChunk = [&](int kc, int buf) {
        const int k0 = kc * 16;
        size_t aoff = (size_t)(m0 + row)*K + k0 + half*8;
        int brow = n0 + row;
        int bp = (brow < Nc) ? 16 : 0;
        size_t boff = (size_t)(bp ? brow : 0)*K + k0 + half*8;
        unsigned dst = (unsigned)__cvta_generic_to_shared(
            smem_raw + buf*24576 + (row*24 + half*8)*2);
        asm volatile("cp.async.cg.shared.global [%0], [%1], 16;\n" :: "r"(dst), "l"(Ah + aoff));
        asm volatile("cp.async.cg.shared.global [%0], [%1], 16;\n" :: "r"(dst + 6144), "l"(Al + aoff));
        asm volatile("cp.async.cg.shared.global [%0], [%1], 16, %2;\n" :: "r"(dst + 12288), "l"(Bh + boff), "r"(bp));
        asm volatile("cp.async.cg.shared.global [%0], [%1], 16, %2;\n" :: "r"(dst + 18432), "l"(Bl + boff), "r"(bp));
    };

    const int nch = K >> 4;
    loadChunk(0, 0);
    asm volatile("cp.async.commit_group;\n");

    for (int kc = 0; kc < nch; kc++) {
        if (kc + 1 < nch) {
            loadChunk(kc + 1, (kc + 1) & 1);
            asm volatile("cp.async.commit_group;\n");
            asm volatile("cp.async.wait_group 1;\n");
        } else {
            asm volatile("cp.async.wait_group 0;\n");
        }
        __syncthreads();
        const __nv_bfloat16* sAh = (const __nv_bfloat16*)(smem_raw + (kc & 1)*24576);
        const __nv_bfloat16* sAl = sAh + 3072;
        const __nv_bfloat16* sBh = sAh + 6144;
        const __nv_bfloat16* sBl = sAh + 9216;

        wmma::fragment<wmma::matrix_a,16,16,16,__nv_bfloat16,wmma::row_major> afh[2], afl[2];
        #pragma unroll
        for (int mi = 0; mi < 2; mi++) {
            int r0 = warp_m*32 + mi*16;
            wmma::load_matrix_sync(afh[mi], sAh + r0*24, 24);
            wmma::load_matrix_sync(afl[mi], sAl + r0*24, 24);
        }
        #pragma unroll
        for (int ni = 0; ni < 4; ni++) {
            int rn = warp_n*64 + ni*16;
            wmma::fragment<wmma::matrix_b,16,16,16,__nv_bfloat16,wmma::col_major> bfh, bfl;
            wmma::load_matrix_sync(bfh, sBh + rn*24, 24);
            wmma::load_matrix_sync(bfl, sBl + rn*24, 24);
            #pragma unroll
            for (int mi = 0; mi < 2; mi++) {
                wmma::mma_sync(c[mi][ni], afh[mi], bfh, c[mi][ni]);
                wmma::mma_sync(c[mi][ni], afl[mi], bfh, c[mi][ni]);
                wmma::mma_sync(c[mi][ni], afh[mi], bfl, c[mi][ni]);
            }
        }
        __syncthreads();
    }

    float* stage = (float*)smem_raw;
    #pragma unroll
    for (int p = 0; p < 2; p++) {
        if (warp_n == p) {
            #pragma unroll
            for (int mi = 0; mi < 2; mi++)
                #pragma unroll
                for (int ni = 0; ni < 4; ni++)
                    wmma::store_matrix_sync(stage + (warp_m*32 + mi*16)*68 + ni*16,
                                            c[mi][ni], 68, wmma::mem_row_major);
        }
        __syncthreads();
        for (int e = tid; e < 8192; e += 256) {
            int r  = e >> 6, cc = e & 63;
            int col = n0 + p*64 + cc;
            if (col < Nc)
                Cf[(size_t)(m0 + r)*Nc + col] = stage[r*68 + cc] + bias[col];
        }
        __syncthreads();
    }
}

// ---------------- feature map from precomputed per-head features -------------
__global__ void __launch_bounds__(128) featmap2_kernel()
{
    int wl = threadIdx.x >> 5;
    int lane = threadIdx.x & 31;
    int gw = blockIdx.x*4 + wl;          // (tok, h) index
    int h  = gw % H_;
    size_t tok = gw / H_;
    int m = lane & 15;
    int isK = lane >> 4;
    float t = g_qkv[tok*QS2_ + isK*256 + h*M_ + m];
    float e = expf(-0.5f*t*t);
    float s = e;
    #pragma unroll
    for (int o = 8; o > 0; o >>= 1) s += __shfl_xor_sync(~0u, s, o);
    float p = e / (s + EPSF);
    if (isK) g_kp[(size_t)gw*M_ + m] = p;
    else     g_qp[(size_t)gw*M_ + m] = p;
}

// ---------------- performer scan --------------------------------------------
__global__ void __launch_bounds__(64) perf_pass1()
{
    int bid = blockIdx.x;
    int c  = bid % CCH;
    int bh = bid / CCH;
    int h = bh % H_, b = bh / H_;
    int t = threadIdx.x;
    float kv[M_], ks[M_];
    #pragma unroll
    for (int m = 0; m < M_; m++) { kv[m] = 0.f; ks[m] = 0.f; }
    int s0 = c*TCH;
    for (int s = s0; s < s0+TCH; s++) {
        size_t tok = (size_t)(b*S_+s);
        float vt = g_qkv[tok*QS2_ + VOFF + h*DK_ + t];
        const float* kpp = &g_kp[(tok*H_ + h)*M_];
        #pragma unroll
        for (int m = 0; m < M_; m++) { float kpv = kpp[m]; kv[m] += kpv*vt; ks[m] += kpv; }
    }
    size_t cb = ((size_t)bh*CCH + c)*M_;
    #pragma unroll
    for (int m = 0; m < M_; m++) g_ckv[(cb+m)*DK_ + t] = kv[m];
    if (t < M_) g_ck[cb + t] = ks[t];
}

__global__ void __launch_bounds__(64) perf_prefix()
{
    int bh = blockIdx.x;
    int t = threadIdx.x;
    for (int m = 0; m < M_; m++) {
        float vals[CCH];
        #pragma unroll
        for (int c = 0; c < CCH; c++)
            vals[c] = g_ckv[(((size_t)bh*CCH + c)*M_ + m)*DK_ + t];
        float acc = 0.f;
        #pragma unroll
        for (int c = 0; c < CCH; c++) { float tmp = vals[c]; vals[c] = acc; acc += tmp; }
        #pragma unroll
        for (int c = 0; c < CCH; c++)
            g_ckv[(((size_t)bh*CCH + c)*M_ + m)*DK_ + t] = vals[c];
    }
    if (t < M_) {
        float vals[CCH];
        #pragma unroll
        for (int c = 0; c < CCH; c++) vals[c] = g_ck[((size_t)bh*CCH + c)*M_ + t];
        float acc = 0.f;
        #pragma unroll
        for (int c = 0; c < CCH; c++) { float tmp = vals[c]; vals[c] = acc; acc += tmp; }
        #pragma unroll
        for (int c = 0; c < CCH; c++) g_ck[((size_t)bh*CCH + c)*M_ + t] = vals[c];
    }
}

__global__ void __launch_bounds__(64) perf_pass2()
{
    int bid = blockIdx.x;
    int c  = bid % CCH;
    int bh = bid / CCH;
    int h = bh % H_, b = bh / H_;
    int t = threadIdx.x;
    float kv[M_], kc[M_];
    size_t cb = ((size_t)bh*CCH + c)*M_;
    #pragma unroll
    for (int m = 0; m < M_; m++) { kv[m] = g_ckv[(cb+m)*DK_ + t]; kc[m] = g_ck[cb+m]; }
    float gate = g_gate[bh];
    int s0 = c*TCH;
    for (int s = s0; s < s0+TCH; s++) {
        size_t tok = (size_t)(b*S_+s);
        float vt = g_qkv[tok*QS2_ + VOFF + h*DK_ + t];
        const float* kpp = &g_kp[(tok*H_ + h)*M_];
        const float* qpp = &g_qp[(tok*H_ + h)*M_];
        float num = 0.f, den = 0.f;
        #pragma unroll
        for (int m = 0; m < M_; m++) {
            float kpv = kpp[m]; kv[m] += kpv*vt; kc[m] += kpv;
            float qpv = qpp[m]; num += qpv*kv[m]; den += qpv*kc[m];
        }
        float o = num / (den + EPSF) * gate;
        size_t oi = tok*D_ + h*DK_ + t;
        __nv_bfloat16 hh = __float2bfloat16(o);
        g_ah[oi] = hh;
        g_al[oi] = __float2bfloat16(o - __bfloat162float(hh));
    }
}

// =============================================================================
extern "C" void kernel_launch(void* const* d_in, const int* in_sizes, int n_in,
                              void* d_out, int out_size)
{
    const int*   ids         = (const int*)  d_in[0];
    const int*   user_ids    = (const int*)  d_in[1];
    const float* id_embed    = (const float*)d_in[2];
    const float* feat_proj   = (const float*)d_in[3];
    const float* gamma       = (const float*)d_in[4];
    const float* gate_logits = (const float*)d_in[5];
    const float* wq          = (const float*)d_in[6];
    const float* wk          = (const float*)d_in[7];
    const float* wv          = (const float*)d_in[8];
    const float* wo          = (const float*)d_in[9];
    const float* omega       = (const float*)d_in[10];
    const float* ln1_a       = (const float*)d_in[11];
    const float* ln1_b       = (const float*)d_in[12];
    const float* ln2_a       = (const float*)d_in[13];
    const float* ln2_b       = (const float*)d_in[14];
    const float* ff_w1       = (const float*)d_in[15];
    const float* ff_b1       = (const float*)d_in[16];
    const float* ff_w2       = (const float*)d_in[17];
    const float* ff_b2       = (const float*)d_in[18];
    const float* fin_a       = (const float*)d_in[19];
    const float* fin_b       = (const float*)d_in[20];
    const float* proj_w      = (const float*)d_in[21];
    const float* proj_b      = (const float*)d_in[22];
    const float* feat_tbl    = (const float*)d_in[23];
    /* d_in[24] = prod_mask (derived as ids>=10) */
    const float* pe          = (const float*)d_in[25];
    float* out = (float*)d_out;

    float *px, *pqkv;
    __nv_bfloat16 *pxh, *pxl, *pah, *pal, *ph1h, *ph1l, *pwh, *pwl;
    cudaGetSymbolAddress((void**)&px,   g_x);
    cudaGetSymbolAddress((void**)&pxh,  g_xh);
    cudaGetSymbolAddress((void**)&pxl,  g_xl);
    cudaGetSymbolAddress((void**)&pqkv, g_qkv);
    cudaGetSymbolAddress((void**)&pah,  g_ah);
    cudaGetSymbolAddress((void**)&pal,  g_al);
    cudaGetSymbolAddress((void**)&ph1h, g_h1h);
    cudaGetSymbolAddress((void**)&ph1l, g_h1l);
    cudaGetSymbolAddress((void**)&pwh,  g_wh);
    cudaGetSymbolAddress((void**)&pwl,  g_wl);

    embtbl_kernel<<<VS_, 256>>>(id_embed, feat_proj, gamma, feat_tbl);
    xinit_kernel<<<(BS_*D_ + 255)/256, 256>>>(ids, pe);
    gate_kernel<<<B_, 32>>>(user_ids, gate_logits);

    // fold omega into wq/wk and split weights
    for (int l = 0; l < L_; l++) {
        const float* om = omega + (size_t)l*M_*DK_;
        featfold_kernel<<<H_, 256>>>(wq + (size_t)l*DD_, om, OFF_QKV + (size_t)l*R_QKV);
        featfold_kernel<<<H_, 256>>>(wk + (size_t)l*DD_, om, OFF_QKV + (size_t)l*R_QKV + (size_t)256*D_);
        wsplit_kernel<<<512, 256>>>((const float4*)(wv + (size_t)l*DD_), DD_/4,
                                    OFF_QKV + (size_t)l*R_QKV + (size_t)VOFF*D_);
    }
    wsplit_kernel<<<1024, 256>>>((const float4*)wo,     (size_t)4*DD_/4,  OFF_WO);
    wsplit_kernel<<<2048, 256>>>((const float4*)ff_w1,  (size_t)16*DD_/4, OFF_FF1);
    wsplit_kernel<<<2048, 256>>>((const float4*)ff_w2,  (size_t)16*DD_/4, OFF_FF2);
    wsplit_kernel<<<128,  256>>>((const float4*)proj_w, (size_t)VT_*D_/4, OFF_PROJ);

    dim3 gQKV(QS2_/128, BS_/128);    // (12, 32)
    dim3 gDD (D_/128,   BS_/128);    // (8, 32)
    dim3 gDF (DFF_/128, BS_/128);    // (32, 32)
    dim3 gVT (1, 32);

    for (int l = 0; l < L_; l++) {
        ln_kernel<<<BS_, 256>>>(px, ln1_a + l*D_, ln1_b + l*D_, pxh, pxl);
        tgemm<0><<<gQKV, 256>>>(pxh, pxl,
                pwh + OFF_QKV + (size_t)l*R_QKV, pwl + OFF_QKV + (size_t)l*R_QKV,
                nullptr, nullptr, pqkv, nullptr, nullptr, QS2_, D_);
        featmap2_kernel<<<BS_*H_/4, 128>>>();
        perf_pass1<<<B_*H_*CCH, 64>>>();
        perf_prefix<<<B_*H_, 64>>>();
        perf_pass2<<<B_*H_*CCH, 64>>>();
        tgemm<3><<<gDD, 256>>>(pah, pal,
                pwh + OFF_WO + (size_t)l*DD_, pwl + OFF_WO + (size_t)l*DD_,
                nullptr, px, px, nullptr, nullptr, D_, D_);
        ln_kernel<<<BS_, 256>>>(px, ln2_a + l*D_, ln2_b + l*D_, pxh, pxl);
        tgemm<2><<<gDF, 256>>>(pxh, pxl,
                pwh + OFF_FF1 + (size_t)l*4*DD_, pwl + OFF_FF1 + (size_t)l*4*DD_,
                ff_b1 + (size_t)l*DFF_, nullptr, nullptr, ph1h, ph1l, DFF_, D_);
        tgemm<4><<<gDD, 256>>>(ph1h, ph1l,
                pwh + OFF_FF2 + (size_t)l*4*DD_, pwl + OFF_FF2 + (size_t)l*4*DD_,
                ff_b2 + (size_t)l*D_, px, px, nullptr, nullptr, D_, DFF_);
    }

    ln_kernel<<<BS_, 256>>>(px, fin_a, fin_b, pxh, pxl);
    bgemm_proj<<<gVT, 256>>>(pxh, pxl, pwh + OFF_PROJ, pwl + OFF_PROJ,
                             proj_b, out, VT_, D_);
}

// round 7
// speedup vs baseline: 3.4137x; 1.3090x over previous
#include <cuda_runtime.h>
#include <cuda_bf16.h>
#include <mma.h>
#include <math.h>
#include <stdint.h>

using namespace nvcuda;

#define B_   2
#define S_   2048
#define D_   1024
#define H_   16
#define DK_  64
#define M_   16
#define L_   4
#define DFF_ 4096
#define VT_  69
#define VS_  69
#define FD_  34
#define BS_  (B_*S_)
#define QS2_ 1536            // packed [qfeat 256 | kfeat 256 | v 1024]
#define VOFF 512
#define CCH  32
#define TCH  64
#define EPSF 1e-6f

#define DD_       ((size_t)D_*D_)
#define R_QKV     ((size_t)QS2_*D_)
#define OFF_QKV   ((size_t)0)
#define OFF_WO    ((size_t)L_*R_QKV)
#define OFF_FF1   (OFF_WO  + (size_t)L_*DD_)
#define OFF_FF2   (OFF_FF1 + (size_t)L_*4*DD_)
#define OFF_PROJ  (OFF_FF2 + (size_t)L_*4*DD_)
#define WTOT      (OFF_PROJ + (size_t)VT_*D_)

// ---------------- scratch ----------------------------------------------------
__device__ __align__(16) float g_emb2[VS_*D_];
__device__ __align__(16) float g_x   [BS_*D_];
__device__ __align__(16) __nv_bfloat16 g_xh[BS_*D_];
__device__ __align__(16) __nv_bfloat16 g_xl[BS_*D_];
__device__ __align__(16) float g_qkv [(size_t)BS_*QS2_];
__device__ __align__(16) float g_qp  [BS_*H_*M_];
__device__ __align__(16) float g_kp  [BS_*H_*M_];
__device__ __align__(16) __nv_bfloat16 g_ah[BS_*D_];
__device__ __align__(16) __nv_bfloat16 g_al[BS_*D_];
__device__ __align__(16) __nv_bfloat16 g_h1h[(size_t)BS_*DFF_];
__device__ __align__(16) __nv_bfloat16 g_h1l[(size_t)BS_*DFF_];
__device__ __align__(16) __nv_bfloat16 g_wh[WTOT];
__device__ __align__(16) __nv_bfloat16 g_wl[WTOT];
__device__ __align__(16) float g_ckv[(size_t)B_*H_*CCH*M_*DK_];
__device__ __align__(16) float g_ck [B_*H_*CCH*M_];
__device__ float g_gate[B_*H_];

// ---------------- vectorized weight split ------------------------------------
__global__ void wsplit_kernel(const float4* __restrict__ src, size_t n4, size_t dstOff)
{
    __nv_bfloat162* wh2 = (__nv_bfloat162*)(g_wh + dstOff);
    __nv_bfloat162* wl2 = (__nv_bfloat162*)(g_wl + dstOff);
    for (size_t i = (size_t)blockIdx.x*blockDim.x + threadIdx.x; i < n4;
         i += (size_t)gridDim.x*blockDim.x) {
        float4 v = src[i];
        __nv_bfloat16 hx = __float2bfloat16(v.x), hy = __float2bfloat16(v.y);
        __nv_bfloat16 hz = __float2bfloat16(v.z), hw = __float2bfloat16(v.w);
        wh2[i*2]   = __halves2bfloat162(hx, hy);
        wh2[i*2+1] = __halves2bfloat162(hz, hw);
        wl2[i*2]   = __halves2bfloat162(__float2bfloat16(v.x - __bfloat162float(hx)),
                                        __float2bfloat16(v.y - __bfloat162float(hy)));
        wl2[i*2+1] = __halves2bfloat162(__float2bfloat16(v.z - __bfloat162float(hz)),
                                        __float2bfloat16(v.w - __bfloat162float(hw)));
    }
}

// ---------------- fold omega into wq/wk (parallel v2) -------------------------
// out[(h,m), d] = sum_dk om[m,dk] * w[h*64+dk, d]
__global__ void __launch_bounds__(128) featfold_kernel(
    const float* __restrict__ w, const float* __restrict__ om, size_t dstRowBase)
{
    int h = blockIdx.y;
    int d = blockIdx.x*128 + threadIdx.x;
    __shared__ float so[M_][DK_];
    for (int i = threadIdx.x; i < M_*DK_; i += 128) so[i/DK_][i%DK_] = om[i];
    __syncthreads();
    float acc[M_];
    #pragma unroll
    for (int m = 0; m < M_; m++) acc[m] = 0.f;
    const float* wp = w + (size_t)h*DK_*D_ + d;
    #pragma unroll 8
    for (int dk = 0; dk < DK_; dk++) {
        float wv = wp[(size_t)dk*D_];
        #pragma unroll
        for (int m = 0; m < M_; m++) acc[m] += so[m][dk]*wv;
    }
    #pragma unroll
    for (int m = 0; m < M_; m++) {
        float v = acc[m];
        __nv_bfloat16 hh = __float2bfloat16(v);
        size_t oi = dstRowBase + (size_t)(h*M_+m)*D_ + d;
        g_wh[oi] = hh;
        g_wl[oi] = __float2bfloat16(v - __bfloat162float(hh));
    }
}

// ---------------- embedding / init / gate ------------------------------------
__global__ void embtbl_kernel(const float* __restrict__ id_embed,
                              const float* __restrict__ feat_proj,
                              const float* __restrict__ gammap,
                              const float* __restrict__ feat_tbl)
{
    int v = blockIdx.x;
    float gscale = gammap[0] * ((v >= 10) ? 1.f : 0.f);
    __shared__ float ft[FD_];
    if (threadIdx.x < FD_) ft[threadIdx.x] = feat_tbl[v*FD_ + threadIdx.x];
    __syncthreads();
    for (int d = threadIdx.x; d < D_; d += blockDim.x) {
        float dot = 0.f;
        #pragma unroll
        for (int f = 0; f < FD_; f++) dot += ft[f] * feat_proj[d*FD_ + f];
        g_emb2[v*D_ + d] = id_embed[(size_t)v*D_ + d] + gscale * dot;
    }
}

__global__ void xinit_kernel(const int* __restrict__ ids, const float* __restrict__ pe)
{
    int idx = blockIdx.x*blockDim.x + threadIdx.x;
    if (idx >= BS_*D_) return;
    int d = idx % D_;
    int bs = idx / D_;
    int s = bs % S_;
    g_x[idx] = g_emb2[ids[bs]*D_ + d] + pe[(size_t)s*D_ + d];
}

__global__ void gate_kernel(const int* __restrict__ user_ids,
                            const float* __restrict__ gl)
{
    int b = blockIdx.x;
    int lane = threadIdx.x;
    float v = (lane < H_) ? gl[(size_t)user_ids[b]*H_ + lane] : -1e30f;
    float mx = v;
    #pragma unroll
    for (int o = 16; o > 0; o >>= 1) mx = fmaxf(mx, __shfl_xor_sync(~0u, mx, o));
    float e = (lane < H_) ? expf(v - mx) : 0.f;
    float s = e;
    #pragma unroll
    for (int o = 16; o > 0; o >>= 1) s += __shfl_xor_sync(~0u, s, o);
    if (lane < H_) g_gate[b*H_ + lane] = e / s;
}

// ---------------- LayerNorm -> bf16 hi/lo ------------------------------------
__global__ void __launch_bounds__(256) ln_kernel(const float* __restrict__ X,
                                                 const float* __restrict__ alpha,
                                                 const float* __restrict__ beta,
                                                 __nv_bfloat16* __restrict__ Yh,
                                                 __nv_bfloat16* __restrict__ Yl)
{
    int row = blockIdx.x;
    const float* x = X + (size_t)row*D_;
    float s = 0.f, s2 = 0.f;
    for (int d = threadIdx.x; d < D_; d += blockDim.x) {
        float v = x[d]; s += v; s2 += v*v;
    }
    __shared__ float red[64];
    #pragma unroll
    for (int o = 16; o > 0; o >>= 1) {
        s  += __shfl_down_sync(~0u, s,  o);
        s2 += __shfl_down_sync(~0u, s2, o);
    }
    int w = threadIdx.x >> 5, lane = threadIdx.x & 31;
    if (lane == 0) { red[w] = s; red[w+32] = s2; }
    __syncthreads();
    if (w == 0) {
        s  = (lane < 8) ? red[lane]    : 0.f;
        s2 = (lane < 8) ? red[lane+32] : 0.f;
        #pragma unroll
        for (int o = 4; o > 0; o >>= 1) {
            s  += __shfl_down_sync(~0u, s,  o);
            s2 += __shfl_down_sync(~0u, s2, o);
        }
        if (lane == 0) { red[0] = s; red[1] = s2; }
    }
    __syncthreads();
    float mu  = red[0] / (float)D_;
    float var = (red[1] - (float)D_*mu*mu) / (float)(D_-1);
    float inv = 1.f / (sqrtf(fmaxf(var, 0.f)) + EPSF);
    for (int d = threadIdx.x; d < D_; d += blockDim.x) {
        float vv = alpha[d] * (x[d] - mu) * inv + beta[d];
        __nv_bfloat16 h = __float2bfloat16(vv);
        Yh[(size_t)row*D_ + d] = h;
        Yl[(size_t)row*D_ + d] = __float2bfloat16(vv - __bfloat162float(h));
    }
}

// =============================================================================
//            mma.sync split-bf16 GEMM  (C = A * B^T), CTA 128x128
// EPI: 0 plain fp32; 2 bias+gelu -> bf16 split; 3 +residual; 4 bias+residual
// =============================================================================
#define STG_BYTES 24576            // per stage: Ah 6144 | Al 6144 | Bh 6144 | Bl 6144
#define ROWB      48               // 24 bf16 per row (16 data + 8 pad)
#define TG4_SMEM  (4u*STG_BYTES)   // 98304

static __device__ __forceinline__ void cpa16s(uint32_t dst, const void* src) {
    asm volatile("cp.async.cg.shared.global [%0], [%1], 16;" :: "r"(dst), "l"(src));
}
static __device__ __forceinline__ void ldm4(uint32_t* d, uint32_t a) {
    asm volatile("ldmatrix.sync.aligned.m8n8.x4.shared.b16 {%0,%1,%2,%3}, [%4];"
                 : "=r"(d[0]), "=r"(d[1]), "=r"(d[2]), "=r"(d[3]) : "r"(a));
}
static __device__ __forceinline__ void mma16816(float* c, const uint32_t* a, const uint32_t* b) {
    asm volatile("mma.sync.aligned.m16n8k16.row.col.f32.bf16.bf16.f32 "
                 "{%0,%1,%2,%3},{%4,%5,%6,%7},{%8,%9},{%0,%1,%2,%3};"
                 : "+f"(c[0]), "+f"(c[1]), "+f"(c[2]), "+f"(c[3])
                 : "r"(a[0]), "r"(a[1]), "r"(a[2]), "r"(a[3]), "r"(b[0]), "r"(b[1]));
}

// shared epilogue (direct from fragments)
template<int EPI>
static __device__ __forceinline__ void tg_epilogue(
    float acc[2][8][4], int m0, int n0, int wm, int wn, int lane,
    const float* bias, const float* res,
    float* Cf, __nv_bfloat16* Ch, __nv_bfloat16* Cl, int Nc)
{
    const int gq = lane >> 2;
    const int qp = lane & 3;
    #pragma unroll
    for (int mi = 0; mi < 2; mi++) {
        #pragma unroll
        for (int nj = 0; nj < 8; nj++) {
            int r0 = m0 + wm*32 + mi*16 + gq;
            int cc = n0 + wn*64 + nj*8 + qp*2;
            #pragma unroll
            for (int hrow = 0; hrow < 2; hrow++) {
                int rr = r0 + hrow*8;
                float v0 = acc[mi][nj][hrow*2 + 0];
                float v1 = acc[mi][nj][hrow*2 + 1];
                size_t gi = (size_t)rr*Nc + cc;
                if (EPI == 2) {
                    v0 += bias[cc]; v1 += bias[cc+1];
                    float x0 = v0, x1 = v1;
                    v0 = 0.5f*x0*(1.f + tanhf(0.7978845608028654f*(x0 + 0.044715f*x0*x0*x0)));
                    v1 = 0.5f*x1*(1.f + tanhf(0.7978845608028654f*(x1 + 0.044715f*x1*x1*x1)));
                    __nv_bfloat16 h0 = __float2bfloat16(v0), h1 = __float2bfloat16(v1);
                    *(__nv_bfloat162*)(Ch + gi) = __halves2bfloat162(h0, h1);
                    *(__nv_bfloat162*)(Cl + gi) = __halves2bfloat162(
                        __float2bfloat16(v0 - __bfloat162float(h0)),
                        __float2bfloat16(v1 - __bfloat162float(h1)));
                } else {
                    if (EPI == 3) { float2 r = *(const float2*)(res + gi); v0 += r.x; v1 += r.y; }
                    if (EPI == 4) {
                        float2 r = *(const float2*)(res + gi);
                        v0 += bias[cc] + r.x; v1 += bias[cc+1] + r.y;
                    }
                    *(float2*)(Cf + gi) = make_float2(v0, v1);
                }
            }
        }
    }
}

// shared per-chunk compute
static __device__ __forceinline__ void tg_compute(
    float acc[2][8][4], uint32_t bb, uint32_t aoff, uint32_t boff)
{
    uint32_t aH[2][4], aL[2][4];
    ldm4(aH[0], bb + aoff);
    ldm4(aH[1], bb + aoff + 16*ROWB);
    ldm4(aL[0], bb + 6144 + aoff);
    ldm4(aL[1], bb + 6144 + aoff + 16*ROWB);

    #pragma unroll
    for (int half = 0; half < 2; half++) {
        uint32_t bH[2][4], bL[2][4];
        uint32_t bo = boff + half*32*ROWB;
        ldm4(bH[0], bb + 12288 + bo);
        ldm4(bH[1], bb + 12288 + bo + 16*ROWB);
        ldm4(bL[0], bb + 18432 + bo);
        ldm4(bL[1], bb + 18432 + bo + 16*ROWB);
        #pragma unroll
        for (int t = 0; t < 4; t++) {
            int nj = half*4 + t;
            const uint32_t* bh = &bH[t >> 1][(t & 1)*2];
            const uint32_t* bl = &bL[t >> 1][(t & 1)*2];
            #pragma unroll
            for (int mi = 0; mi < 2; mi++) {
                mma16816(acc[mi][nj], aH[mi], bh);
                mma16816(acc[mi][nj], aL[mi], bh);
                mma16816(acc[mi][nj], aH[mi], bl);
            }
        }
    }
}

// ---- 4-stage, single-sync-per-chunk, dynamic smem ---------------------------
template<int EPI>
__global__ void __launch_bounds__(256, 2) tgemm4(
    const __nv_bfloat16* __restrict__ Ah, const __nv_bfloat16* __restrict__ Al,
    const __nv_bfloat16* __restrict__ Bh, const __nv_bfloat16* __restrict__ Bl,
    const float* __restrict__ bias, const float* __restrict__ res,
    float* __restrict__ Cf, __nv_bfloat16* __restrict__ Ch, __nv_bfloat16* __restrict__ Cl,
    int Nc, int K)
{
    extern __shared__ __align__(16) unsigned char sm4[];
    const uint32_t smB = (uint32_t)__cvta_generic_to_shared(sm4);

    const int tid  = threadIdx.x;
    const int wid  = tid >> 5;
    const int lane = tid & 31;
    const int wm   = wid >> 1;
    const int wn   = wid & 1;
    const int m0 = blockIdx.y * 128;
    const int n0 = blockIdx.x * 128;

    float acc[2][8][4];
    #pragma unroll
    for (int i = 0; i < 2; i++)
        #pragma unroll
        for (int j = 0; j < 8; j++)
            #pragma unroll
            for (int q = 0; q < 4; q++) acc[i][j][q] = 0.f;

    const int crow = tid >> 1, cq = tid & 1;
    const uint32_t cdst = (uint32_t)(crow*ROWB + cq*16);
    const size_t  asrc = (size_t)(m0 + crow)*K + cq*8;
    const size_t  bsrc = (size_t)(n0 + crow)*K + cq*8;

    const uint32_t aoff = (uint32_t)((wm*32 + (lane & 15))*ROWB + (lane >> 4)*16);
    const uint32_t boff = (uint32_t)((wn*64 + ((lane >> 4) << 3) + (lane & 7))*ROWB
                                     + ((lane >> 3) & 1)*16);

    auto loadChunk = [&](int c, int buf) {
        uint32_t bb = smB + (uint32_t)buf*STG_BYTES + cdst;
        int k0 = c*16;
        cpa16s(bb,         Ah + asrc + k0);
        cpa16s(bb +  6144, Al + asrc + k0);
        cpa16s(bb + 12288, Bh + bsrc + k0);
        cpa16s(bb + 18432, Bl + bsrc + k0);
        asm volatile("cp.async.commit_group;");
    };

    const int nch = K >> 4;
    loadChunk(0, 0);
    loadChunk(1, 1);

    for (int c = 0; c < nch; c++) {
        if (c + 2 < nch) {
            loadChunk(c + 2, (c + 2) & 3);
            asm volatile("cp.async.wait_group 2;");
        } else if (c + 1 < nch) {
            asm volatile("cp.async.wait_group 1;");
        } else {
            asm volatile("cp.async.wait_group 0;");
        }
        __syncthreads();
        tg_compute(acc, smB + (uint32_t)(c & 3)*STG_BYTES, aoff, boff);
    }

    tg_epilogue<EPI>(acc, m0, n0, wm, wn, lane, bias, res, Cf, Ch, Cl, Nc);
}

// ---- 2-stage static-smem fallback (proven R6 path) --------------------------
template<int EPI>
__global__ void __launch_bounds__(256, 2) tgemm2(
    const __nv_bfloat16* __restrict__ Ah, const __nv_bfloat16* __restrict__ Al,
    const __nv_bfloat16* __restrict__ Bh, const __nv_bfloat16* __restrict__ Bl,
    const float* __restrict__ bias, const float* __restrict__ res,
    float* __restrict__ Cf, __nv_bfloat16* __restrict__ Ch, __nv_bfloat16* __restrict__ Cl,
    int Nc, int K)
{
    __shared__ __align__(16) unsigned char sm[2*STG_BYTES];
    const uint32_t smB = (uint32_t)__cvta_generic_to_shared(sm);

    const int tid  = threadIdx.x;
    const int wid  = tid >> 5;
    const int lane = tid & 31;
    const int wm   = wid >> 1;
    const int wn   = wid & 1;
    const int m0 = blockIdx.y * 128;
    const int n0 = blockIdx.x * 128;

    float acc[2][8][4];
    #pragma unroll
    for (int i = 0; i < 2; i++)
        #pragma unroll
        for (int j = 0; j < 8; j++)
            #pragma unroll
            for (int q = 0; q < 4; q++) acc[i][j][q] = 0.f;

    const int crow = tid >> 1, cq = tid & 1;
    const uint32_t cdst = (uint32_t)(crow*ROWB + cq*16);
    const size_t  asrc = (size_t)(m0 + crow)*K + cq*8;
    const size_t  bsrc = (size_t)(n0 + crow)*K + cq*8;

    const uint32_t aoff = (uint32_t)((wm*32 + (lane & 15))*ROWB + (lane >> 4)*16);
    const uint32_t boff = (uint32_t)((wn*64 + ((lane >> 4) << 3) + (lane & 7))*ROWB
                                     + ((lane >> 3) & 1)*16);

    auto loadChunk = [&](int c, int buf) {
        uint32_t bb = smB + (uint32_t)buf*STG_BYTES + cdst;
        int k0 = c*16;
        cpa16s(bb,         Ah + asrc + k0);
        cpa16s(bb +  6144, Al + asrc + k0);
        cpa16s(bb + 12288, Bh + bsrc + k0);
        cpa16s(bb + 18432, Bl + bsrc + k0);
        asm volatile("cp.async.commit_group;");
    };

    const int nch = K >> 4;
    loadChunk(0, 0);

    for (int c = 0; c < nch; c++) {
        if (c + 1 < nch) {
            loadChunk(c + 1, (c + 1) & 1);
            asm volatile("cp.async.wait_group 1;");
        } else {
            asm volatile("cp.async.wait_group 0;");
        }
        __syncthreads();
        tg_compute(acc, smB + (uint32_t)(c & 1)*STG_BYTES, aoff, boff);
        __syncthreads();
    }

    tg_epilogue<EPI>(acc, m0, n0, wm, wn, lane, bias, res, Cf, Ch, Cl, Nc);
}

// ---------------- wmma GEMM for the tiny VT=69 projection --------------------
__global__ void __launch_bounds__(256, 2) bgemm_proj(
    const __nv_bfloat16* __restrict__ Ah, const __nv_bfloat16* __restrict__ Al,
    const __nv_bfloat16* __restrict__ Bh, const __nv_bfloat16* __restrict__ Bl,
    const float* __restrict__ bias, float* __restrict__ Cf, int Nc, int K)
{
    __shared__ __align__(16) unsigned char smem_raw[49152];
    const int tid = threadIdx.x;
    const int warpId = tid >> 5;
    const int warp_m = warpId & 3;
    const int warp_n = warpId >> 2;
    const int m0 = blockIdx.y * 128;
    const int n0 = blockIdx.x * 128;

    wmma::fragment<wmma::accumulator,16,16,16,float> c[2][4];
    #pragma unroll
    for (int i = 0; i < 2; i++)
        #pragma unroll
        for (int j = 0; j < 4; j++) wmma::fill_fragment(c[i][j], 0.f);

    const int row  = tid >> 1;
    const int half = tid & 1;

    auto loadChunk = [&](int kc, int buf) {
        const int k0 = kc * 16;
        size_t aoff = (size_t)(m0 + row)*K + k0 + half*8;
        int brow = n0 + row;
        int bp = (brow < Nc) ? 16 : 0;
        size_t boff = (size_t)(bp ? brow : 0)*K + k0 + half*8;
        unsigned dst = (unsigned)__cvta_generic_to_shared(
            smem_raw + buf*24576 + (row*24 + half*8)*2);
        asm volatile("cp.async.cg.shared.global [%0], [%1], 16;\n" :: "r"(dst), "l"(Ah + aoff));
        asm volatile("cp.async.cg.shared.global [%0], [%1], 16;\n" :: "r"(dst + 6144), "l"(Al + aoff));
        asm volatile("cp.async.cg.shared.global [%0], [%1], 16, %2;\n" :: "r"(dst + 12288), "l"(Bh + boff), "r"(bp));
        asm volatile("cp.async.cg.shared.global [%0], [%1], 16, %2;\n" :: "r"(dst + 18432), "l"(Bl + boff), "r"(bp));
    };

    const int nch = K >> 4;
    loadChunk(0, 0);
    asm volatile("cp.async.commit_group;\n");

    for (int kc = 0; kc < nch; kc++) {
        if (kc + 1 < nch) {
            loadChunk(kc + 1, (kc + 1) & 1);
            asm volatile("cp.async.commit_group;\n");
            asm volatile("cp.async.wait_group 1;\n");
        } else {
            asm volatile("cp.async.wait_group 0;\n");
        }
        __syncthreads();
        const __nv_bfloat16* sAh = (const __nv_bfloat16*)(smem_raw + (kc & 1)*24576);
        const __nv_bfloat16* sAl = sAh + 3072;
        const __nv_bfloat16* sBh = sAh + 6144;
        const __nv_bfloat16* sBl = sAh + 9216;

        wmma::fragment<wmma::matrix_a,16,16,16,__nv_bfloat16,wmma::row_major> afh[2], afl[2];
        #pragma unroll
        for (int mi = 0; mi < 2; mi++) {
            int r0 = warp_m*32 + mi*16;
            wmma::load_matrix_sync(afh[mi], sAh + r0*24, 24);
            wmma::load_matrix_sync(afl[mi], sAl + r0*24, 24);
        }
        #pragma unroll
        for (int ni = 0; ni < 4; ni++) {
            int rn = warp_n*64 + ni*16;
            wmma::fragment<wmma::matrix_b,16,16,16,__nv_bfloat16,wmma::col_major> bfh, bfl;
            wmma::load_matrix_sync(bfh, sBh + rn*24, 24);
            wmma::load_matrix_sync(bfl, sBl + rn*24, 24);
            #pragma unroll
            for (int mi = 0; mi < 2; mi++) {
                wmma::mma_sync(c[mi][ni], afh[mi], bfh, c[mi][ni]);
                wmma::mma_sync(c[mi][ni], afl[mi], bfh, c[mi][ni]);
                wmma::mma_sync(c[mi][ni], afh[mi], bfl, c[mi][ni]);
            }
        }
        __syncthreads();
    }

    float* stage = (float*)smem_raw;
    #pragma unroll
    for (int p = 0; p < 2; p++) {
        if (warp_n == p) {
            #pragma unroll
            for (int mi = 0; mi < 2; mi++)
                #pragma unroll
                for (int ni = 0; ni < 4; ni++)
                    wmma::store_matrix_sync(stage + (warp_m*32 + mi*16)*68 + ni*16,
                                            c[mi][ni], 68, wmma::mem_row_major);
        }
        __syncthreads();
        for (int e = tid; e < 8192; e += 256) {
            int r  = e >> 6, cc = e & 63;
            int col = n0 + p*64 + cc;
            if (col < Nc)
                Cf[(size_t)(m0 + r)*Nc + col] = stage[r*68 + cc] + bias[col];
        }
        __syncthreads();
    }
}

// ---------------- feature map from precomputed per-head features -------------
__global__ void __launch_bounds__(128) featmap2_kernel()
{
    int wl = threadIdx.x >> 5;
    int lane = threadIdx.x & 31;
    int gw = blockIdx.x*4 + wl;
    int h  = gw % H_;
    size_t tok = gw / H_;
    int m = lane & 15;
    int isK = lane >> 4;
    float t = g_qkv[tok*QS2_ + isK*256 + h*M_ + m];
    float e = expf(-0.5f*t*t);
    float s = e;
    #pragma unroll
    for (int o = 8; o > 0; o >>= 1) s += __shfl_xor_sync(~0u, s, o);
    float p = e / (s + EPSF);
    if (isK) g_kp[(size_t)gw*M_ + m] = p;
    else     g_qp[(size_t)gw*M_ + m] = p;
}

// ---------------- performer scan --------------------------------------------
__global__ void __launch_bounds__(64) perf_pass1()
{
    int bid = blockIdx.x;
    int c  = bid % CCH;
    int bh = bid / CCH;
    int h = bh % H_, b = bh / H_;
    int t = threadIdx.x;
    float kv[M_], ks[M_];
    #pragma unroll
    for (int m = 0; m < M_; m++) { kv[m] = 0.f; ks[m] = 0.f; }
    int s0 = c*TCH;
    for (int s = s0; s < s0+TCH; s++) {
        size_t tok = (size_t)(b*S_+s);
        float vt = g_qkv[tok*QS2_ + VOFF + h*DK_ + t];
        const float* kpp = &g_kp[(tok*H_ + h)*M_];
        #pragma unroll
        for (int m = 0; m < M_; m++) { float kpv = kpp[m]; kv[m] += kpv*vt; ks[m] += kpv; }
    }
    size_t cb = ((size_t)bh*CCH + c)*M_;
    #pragma unroll
    for (int m = 0; m < M_; m++) g_ckv[(cb+m)*DK_ + t] = kv[m];
    if (t < M_) g_ck[cb + t] = ks[t];
}

__global__ void __launch_bounds__(64) perf_prefix()
{
    int bh = blockIdx.x;
    int t = threadIdx.x;
    for (int m = 0; m < M_; m++) {
        float vals[CCH];
        #pragma unroll
        for (int c = 0; c < CCH; c++)
            vals[c] = g_ckv[(((size_t)bh*CCH + c)*M_ + m)*DK_ + t];
        float acc = 0.f;
        #pragma unroll
        for (int c = 0; c < CCH; c++) { float tmp = vals[c]; vals[c] = acc; acc += tmp; }
        #pragma unroll
        for (int c = 0; c < CCH; c++)
            g_ckv[(((size_t)bh*CCH + c)*M_ + m)*DK_ + t] = vals[c];
    }
    if (t < M_) {
        float vals[CCH];
        #pragma unroll
        for (int c = 0; c < CCH; c++) vals[c] = g_ck[((size_t)bh*CCH + c)*M_ + t];
        float acc = 0.f;
        #pragma unroll
        for (int c = 0; c < CCH; c++) { float tmp = vals[c]; vals[c] = acc; acc += tmp; }
        #pragma unroll
        for (int c = 0; c < CCH; c++) g_ck[((size_t)bh*CCH + c)*M_ + t] = vals[c];
    }
}

__global__ void __launch_bounds__(64) perf_pass2()
{
    int bid = blockIdx.x;
    int c  = bid % CCH;
    int bh = bid / CCH;
    int h = bh % H_, b = bh / H_;
    int t = threadIdx.x;
    float kv[M_], kc[M_];
    size_t cb = ((size_t)bh*CCH + c)*M_;
    #pragma unroll
    for (int m = 0; m < M_; m++) { kv[m] = g_ckv[(cb+m)*DK_ + t]; kc[m] = g_ck[cb+m]; }
    float gate = g_gate[bh];
    int s0 = c*TCH;
    for (int s = s0; s < s0+TCH; s++) {
        size_t tok = (size_t)(b*S_+s);
        float vt = g_qkv[tok*QS2_ + VOFF + h*DK_ + t];
        const float* kpp = &g_kp[(tok*H_ + h)*M_];
        const float* qpp = &g_qp[(tok*H_ + h)*M_];
        float num = 0.f, den = 0.f;
        #pragma unroll
        for (int m = 0; m < M_; m++) {
            float kpv = kpp[m]; kv[m] += kpv*vt; kc[m] += kpv;
            float qpv = qpp[m]; num += qpv*kv[m]; den += qpv*kc[m];
        }
        float o = num / (den + EPSF) * gate;
        size_t oi = tok*D_ + h*DK_ + t;
        __nv_bfloat16 hh = __float2bfloat16(o);
        g_ah[oi] = hh;
        g_al[oi] = __float2bfloat16(o - __bfloat162float(hh));
    }
}

// =============================================================================
extern "C" void kernel_launch(void* const* d_in, const int* in_sizes, int n_in,
                              void* d_out, int out_size)
{
    const int*   ids         = (const int*)  d_in[0];
    const int*   user_ids    = (const int*)  d_in[1];
    const float* id_embed    = (const float*)d_in[2];
    const float* feat_proj   = (const float*)d_in[3];
    const float* gamma       = (const float*)d_in[4];
    const float* gate_logits = (const float*)d_in[5];
    const float* wq          = (const float*)d_in[6];
    const float* wk          = (const float*)d_in[7];
    const float* wv          = (const float*)d_in[8];
    const float* wo          = (const float*)d_in[9];
    const float* omega       = (const float*)d_in[10];
    const float* ln1_a       = (const float*)d_in[11];
    const float* ln1_b       = (const float*)d_in[12];
    const float* ln2_a       = (const float*)d_in[13];
    const float* ln2_b       = (const float*)d_in[14];
    const float* ff_w1       = (const float*)d_in[15];
    const float* ff_b1       = (const float*)d_in[16];
    const float* ff_w2       = (const float*)d_in[17];
    const float* ff_b2       = (const float*)d_in[18];
    const float* fin_a       = (const float*)d_in[19];
    const float* fin_b       = (const float*)d_in[20];
    const float* proj_w      = (const float*)d_in[21];
    const float* proj_b      = (const float*)d_in[22];
    const float* feat_tbl    = (const float*)d_in[23];
    /* d_in[24] = prod_mask (derived as ids>=10) */
    const float* pe          = (const float*)d_in[25];
    float* out = (float*)d_out;

    float *px, *pqkv;
    __nv_bfloat16 *pxh, *pxl, *pah, *pal, *ph1h, *ph1l, *pwh, *pwl;
    cudaGetSymbolAddress((void**)&px,   g_x);
    cudaGetSymbolAddress((void**)&pxh,  g_xh);
    cudaGetSymbolAddress((void**)&pxl,  g_xl);
    cudaGetSymbolAddress((void**)&pqkv, g_qkv);
    cudaGetSymbolAddress((void**)&pah,  g_ah);
    cudaGetSymbolAddress((void**)&pal,  g_al);
    cudaGetSymbolAddress((void**)&ph1h, g_h1h);
    cudaGetSymbolAddress((void**)&ph1l, g_h1l);
    cudaGetSymbolAddress((void**)&pwh,  g_wh);
    cudaGetSymbolAddress((void**)&pwl,  g_wl);

    // opt-in to 96KB dynamic smem for the 4-stage GEMM (idempotent, deterministic)
    bool deep = true;
    deep &= (cudaFuncSetAttribute(tgemm4<0>, cudaFuncAttributeMaxDynamicSharedMemorySize, TG4_SMEM) == cudaSuccess);
    deep &= (cudaFuncSetAttribute(tgemm4<2>, cudaFuncAttributeMaxDynamicSharedMemorySize, TG4_SMEM) == cudaSuccess);
    deep &= (cudaFuncSetAttribute(tgemm4<3>, cudaFuncAttributeMaxDynamicSharedMemorySize, TG4_SMEM) == cudaSuccess);
    deep &= (cudaFuncSetAttribute(tgemm4<4>, cudaFuncAttributeMaxDynamicSharedMemorySize, TG4_SMEM) == cudaSuccess);

    embtbl_kernel<<<VS_, 256>>>(id_embed, feat_proj, gamma, feat_tbl);
    xinit_kernel<<<(BS_*D_ + 255)/256, 256>>>(ids, pe);
    gate_kernel<<<B_, 32>>>(user_ids, gate_logits);

    dim3 gFold(D_/128, H_);          // (8, 16)
    for (int l = 0; l < L_; l++) {
        const float* om = omega + (size_t)l*M_*DK_;
        featfold_kernel<<<gFold, 128>>>(wq + (size_t)l*DD_, om, OFF_QKV + (size_t)l*R_QKV);
        featfold_kernel<<<gFold, 128>>>(wk + (size_t)l*DD_, om, OFF_QKV + (size_t)l*R_QKV + (size_t)256*D_);
        wsplit_kernel<<<512, 256>>>((const float4*)(wv + (size_t)l*DD_), DD_/4,
                                    OFF_QKV + (size_t)l*R_QKV + (size_t)VOFF*D_);
    }
    wsplit_kernel<<<1024, 256>>>((const float4*)wo,     (size_t)4*DD_/4,  OFF_WO);
    wsplit_kernel<<<2048, 256>>>((const float4*)ff_w1,  (size_t)16*DD_/4, OFF_FF1);
    wsplit_kernel<<<2048, 256>>>((const float4*)ff_w2,  (size_t)16*DD_/4, OFF_FF2);
    wsplit_kernel<<<128,  256>>>((const float4*)proj_w, (size_t)VT_*D_/4, OFF_PROJ);

    dim3 gQKV(QS2_/128, BS_/128);    // (12, 32)
    dim3 gDD (D_/128,   BS_/128);    // (8, 32)
    dim3 gDF (DFF_/128, BS_/128);    // (32, 32)
    dim3 gVT (1, 32);

    #define RUN_TG(E, GRID, AH, AL, BH, BL, BI, RS, CF, CH, CL, NC, KK)            \
        do {                                                                        \
            if (deep) tgemm4<E><<<GRID, 256, TG4_SMEM>>>(AH, AL, BH, BL, BI, RS,    \
                                                         CF, CH, CL, NC, KK);       \
            else      tgemm2<E><<<GRID, 256>>>(AH, AL, BH, BL, BI, RS,              \
                                               CF, CH, CL, NC, KK);                 \
        } while (0)

    for (int l = 0; l < L_; l++) {
        ln_kernel<<<BS_, 256>>>(px, ln1_a + l*D_, ln1_b + l*D_, pxh, pxl);
        RUN_TG(0, gQKV, pxh, pxl,
               pwh + OFF_QKV + (size_t)l*R_QKV, pwl + OFF_QKV + (size_t)l*R_QKV,
               (const float*)nullptr, (const float*)nullptr,
               pqkv, (__nv_bfloat16*)nullptr, (__nv_bfloat16*)nullptr, QS2_, D_);
        featmap2_kernel<<<BS_*H_/4, 128>>>();
        perf_pass1<<<B_*H_*CCH, 64>>>();
        perf_prefix<<<B_*H_, 64>>>();
        perf_pass2<<<B_*H_*CCH, 64>>>();
        RUN_TG(3, gDD, pah, pal,
               pwh + OFF_WO + (size_t)l*DD_, pwl + OFF_WO + (size_t)l*DD_,
               (const float*)nullptr, px,
               px, (__nv_bfloat16*)nullptr, (__nv_bfloat16*)nullptr, D_, D_);
        ln_kernel<<<BS_, 256>>>(px, ln2_a + l*D_, ln2_b + l*D_, pxh, pxl);
        RUN_TG(2, gDF, pxh, pxl,
               pwh + OFF_FF1 + (size_t)l*4*DD_, pwl + OFF_FF1 + (size_t)l*4*DD_,
               ff_b1 + (size_t)l*DFF_, (const float*)nullptr,
               (float*)nullptr, ph1h, ph1l, DFF_, D_);
        RUN_TG(4, gDD, ph1h, ph1l,
               pwh + OFF_FF2 + (size_t)l*4*DD_, pwl + OFF_FF2 + (size_t)l*4*DD_,
               ff_b2 + (size_t)l*D_, px,
               px, (__nv_bfloat16*)nullptr, (__nv_bfloat16*)nullptr, D_, DFF_);
    }

    ln_kernel<<<BS_, 256>>>(px, fin_a, fin_b, pxh, pxl);
    bgemm_proj<<<gVT, 256>>>(pxh, pxl, pwh + OFF_PROJ, pwl + OFF_PROJ,
                             proj_b, out, VT_, D_);
}